// round 11
// baseline (speedup 1.0000x reference)
#include <cuda_runtime.h>
#include <cuda_fp16.h>
#include <cstdint>

#define HQ 4
#define NQ 4096
#define NK 8192
#define KVS 4           // kv splits
#define KVLEN (NK / KVS)

// ---------------- scratch (allocation-free __device__ globals) -------------
__device__ __align__(16) __half g_qh [HQ * NQ * 64];    // q fp16 (rope'd, /8)
__device__ __align__(16) __half g_kh [HQ * NK * 64];    // k fp16 (rope'd)
__device__ __align__(16) __half g_vthi[HQ * 64 * NK];   // [h][d][n]
__device__ __align__(16) float g_po[KVS * HQ * NQ * 64]; // partial O (unnormalized)
__device__ __align__(16) float g_pl[KVS * HQ * NQ];      // partial row sums

// ---------------- helpers ---------------------------------------------------
__device__ __forceinline__ uint32_t smem_u32(const void* p) {
    uint32_t a;
    asm("{ .reg .u64 t; cvta.to.shared.u64 t, %1; cvt.u32.u64 %0, t; }" : "=r"(a) : "l"(p));
    return a;
}
__device__ __forceinline__ unsigned pkh(float hi, float lo) {
    unsigned r;
    asm("cvt.rn.f16x2.f32 %0, %1, %2;" : "=r"(r) : "f"(hi), "f"(lo));
    return r;
}
__device__ __forceinline__ float ex2(float x) {
    float r;
    asm("ex2.approx.f32 %0, %1;" : "=f"(r) : "f"(x));
    return r;
}
__device__ __forceinline__ float tf32r(float x) {
    uint32_t r;
    asm("cvt.rna.tf32.f32 %0, %1;" : "=r"(r) : "f"(x));
    return __uint_as_float(r);
}

#define LDX4(r, a) asm volatile( \
    "ldmatrix.sync.aligned.m8n8.x4.shared.b16 {%0,%1,%2,%3}, [%4];" \
    : "=r"((r)[0]), "=r"((r)[1]), "=r"((r)[2]), "=r"((r)[3]) : "r"(a))

#define MMAH(c, a, b0, b1) asm volatile( \
    "mma.sync.aligned.m16n8k16.row.col.f32.f16.f16.f32 " \
    "{%0,%1,%2,%3},{%4,%5,%6,%7},{%8,%9},{%0,%1,%2,%3};" \
    : "+f"((c)[0]), "+f"((c)[1]), "+f"((c)[2]), "+f"((c)[3]) \
    : "r"((a)[0]), "r"((a)[1]), "r"((a)[2]), "r"((a)[3]), "r"(b0), "r"(b1))

#define MMAT(c, a, b0, b1) asm volatile( \
    "mma.sync.aligned.m16n8k8.row.col.f32.tf32.tf32.f32 " \
    "{%0,%1,%2,%3},{%4,%5,%6,%7},{%8,%9},{%0,%1,%2,%3};" \
    : "+f"((c)[0]), "+f"((c)[1]), "+f"((c)[2]), "+f"((c)[3]) \
    : "r"((a)[0]), "r"((a)[1]), "r"((a)[2]), "r"((a)[3]), "r"(b0), "r"(b1))

#define CP16(dst, src) asm volatile( \
    "cp.async.cg.shared.global [%0], [%1], 16;" :: "r"(dst), "l"(src))
#define CPCOMMIT() asm volatile("cp.async.commit_group;" ::: "memory")
#define CPWAIT(n)  asm volatile("cp.async.wait_group %0;" :: "n"(n) : "memory")

// ---------------- tf32 tensor-core projection GEMM -------------------------
// CTA: 64 rows x 256 cols, 256 threads (8 warps, 2x4, warp tile 32x64).
// K-chunk 16, double-buffered smem; staging converts fp32 -> tf32 (rna).
// phase 0 (grid 320): bx<64 Q, bx<192 K, else V. phase 1 (grid 64): O proj.
// Epilogues: 0 rope+/8+fp16 -> g_qh; 1 rope+fp16 -> g_kh;
//            2 +bias, fp16, transpose -> g_vthi; 3 combine+norm prologue -> out.
#define PROJ_SMEM 51200  // 2*64*20*4 + 2*256*20*4

__global__ __launch_bounds__(256, 1) void mm_kernel(
    const float* __restrict__ Aq, const float* __restrict__ Ak,
    const float* __restrict__ Av,
    const float* __restrict__ Wq, const float* __restrict__ bq,
    const float* __restrict__ Wk, const float* __restrict__ bk,
    const float* __restrict__ Wv, const float* __restrict__ bv,
    const float* __restrict__ Wo, const float* __restrict__ bo,
    float* __restrict__ outp, const int* __restrict__ nex_ptr, int phase)
{
    extern __shared__ float smf[];
    __shared__ float linv[256];
    float* sA = smf;            // [2][64*20]
    float* sW = smf + 2560;     // [2][256*20]

    const int tid  = threadIdx.x;
    const int lane = tid & 31, w = tid >> 5;
    const int wr = w >> 2, wc = w & 3;
    const int r = lane >> 2, cl = lane & 3;

    int mode, m0, K;
    const float *A = Aq, *W, *bias;
    if (phase == 1) {
        mode = 3; m0 = blockIdx.x << 6; K = 256; W = Wo; bias = bo;
    } else {
        int bx = blockIdx.x;
        if (bx < 64)       { mode = 0; m0 = bx << 6;         K = 256; A = Aq; W = Wq; bias = bq; }
        else if (bx < 192) { mode = 1; m0 = (bx - 64) << 6;  K = 64;  A = Ak; W = Wk; bias = bk; }
        else               { mode = 2; m0 = (bx - 192) << 6; K = 64;  A = Av; W = Wv; bias = bv; }
    }

    if (mode == 3) {
        int hh = tid >> 6, rl = tid & 63;
        float l = 0.f;
#pragma unroll
        for (int z = 0; z < KVS; z++)
            l += g_pl[(size_t)(z * HQ + hh) * NQ + m0 + rl];
        linv[tid] = 1.0f / l;
        __syncthreads();
    }

    const int NCH = K >> 4;
    float4 ra;
    float4 rw[4];

    auto ldg_stage = [&](int kc) {
        if (mode != 3) {
            ra = *(const float4*)&A[(size_t)(m0 + (tid >> 2)) * K + kc + (tid & 3) * 4];
        } else {
            int k = kc + (tid & 3) * 4;
            int hh = k >> 6, d = k & 63;
            int row = tid >> 2;
            size_t base = ((size_t)hh * NQ + m0 + row) * 64 + d;
            float4 s = *(const float4*)&g_po[base];
#pragma unroll
            for (int z = 1; z < KVS; z++) {
                float4 p = *(const float4*)&g_po[(size_t)z * (HQ * NQ * 64) + base];
                s.x += p.x; s.y += p.y; s.z += p.z; s.w += p.w;
            }
            float iv = linv[hh * 64 + row];
            ra = make_float4(s.x * iv, s.y * iv, s.z * iv, s.w * iv);
        }
        int kk = tid >> 6, nn = (tid & 63) * 4;
#pragma unroll
        for (int i = 0; i < 4; i++)
            rw[i] = *(const float4*)&W[(size_t)(kc + kk + i * 4) * 256 + nn];
    };

    auto sts_stage = [&](int buf) {
        float* pA = sA + buf * 1280 + (tid >> 2) * 20 + (tid & 3) * 4;
        *(float4*)pA = make_float4(tf32r(ra.x), tf32r(ra.y), tf32r(ra.z), tf32r(ra.w));
        float* pW = sW + buf * 5120;
        int kk = tid >> 6, nn = (tid & 63) * 4;
#pragma unroll
        for (int i = 0; i < 4; i++) {
            int kq = kk + i * 4;
            pW[(nn + 0) * 20 + kq] = tf32r(rw[i].x);
            pW[(nn + 1) * 20 + kq] = tf32r(rw[i].y);
            pW[(nn + 2) * 20 + kq] = tf32r(rw[i].z);
            pW[(nn + 3) * 20 + kq] = tf32r(rw[i].w);
        }
    };

    float cf[2][8][4];
#pragma unroll
    for (int mt = 0; mt < 2; mt++)
#pragma unroll
        for (int nt = 0; nt < 8; nt++)
#pragma unroll
            for (int e = 0; e < 4; e++) cf[mt][nt][e] = 0.f;

    ldg_stage(0);
    sts_stage(0);
    __syncthreads();

    for (int ch = 0; ch < NCH; ch++) {
        if (ch + 1 < NCH) ldg_stage((ch + 1) << 4);
        const float* bA = sA + (ch & 1) * 1280;
        const float* bW = sW + (ch & 1) * 5120;
#pragma unroll
        for (int k8 = 0; k8 < 16; k8 += 8) {
            uint32_t af[2][4];
#pragma unroll
            for (int mt = 0; mt < 2; mt++) {
                const float* pa = bA + (wr * 32 + mt * 16 + r) * 20 + k8 + cl;
                af[mt][0] = __float_as_uint(pa[0]);
                af[mt][1] = __float_as_uint(pa[160]);
                af[mt][2] = __float_as_uint(pa[4]);
                af[mt][3] = __float_as_uint(pa[164]);
            }
#pragma unroll
            for (int nt = 0; nt < 8; nt++) {
                const float* pb = bW + (wc * 64 + nt * 8 + r) * 20 + k8 + cl;
                uint32_t b0 = __float_as_uint(pb[0]);
                uint32_t b1 = __float_as_uint(pb[4]);
                MMAT(cf[0][nt], af[0], b0, b1);
                MMAT(cf[1][nt], af[1], b0, b1);
            }
        }
        if (ch + 1 < NCH) sts_stage((ch + 1) & 1);
        __syncthreads();
    }

    // ---- epilogues ----
    const int cc2 = cl * 2;
    float b0v[8], b1v[8];
#pragma unroll
    for (int nt = 0; nt < 8; nt++) {
        int n = wc * 64 + nt * 8 + cc2;
        b0v[nt] = bias[n];
        b1v[nt] = bias[n + 1];
    }

    if (mode == 3) {
#pragma unroll
        for (int mt = 0; mt < 2; mt++)
#pragma unroll
            for (int rr = 0; rr < 2; rr++) {
                int row = m0 + wr * 32 + mt * 16 + r + rr * 8;
#pragma unroll
                for (int nt = 0; nt < 8; nt++) {
                    int n = wc * 64 + nt * 8 + cc2;
                    *(float2*)&outp[(size_t)row * 256 + n] = make_float2(
                        cf[mt][nt][rr * 2] + b0v[nt],
                        cf[mt][nt][rr * 2 + 1] + b1v[nt]);
                }
            }
        return;
    }

    if (mode == 2) {
        __half* tb = (__half*)smf;   // [64][264]
#pragma unroll
        for (int mt = 0; mt < 2; mt++)
#pragma unroll
            for (int rr = 0; rr < 2; rr++) {
                int rowl = wr * 32 + mt * 16 + r + rr * 8;
#pragma unroll
                for (int nt = 0; nt < 8; nt++) {
                    int n = wc * 64 + nt * 8 + cc2;
                    *(unsigned*)&tb[rowl * 264 + n] = pkh(
                        cf[mt][nt][rr * 2 + 1] + b1v[nt],
                        cf[mt][nt][rr * 2] + b0v[nt]);
                }
            }
        __syncthreads();
        unsigned ur[32];
#pragma unroll
        for (int j = 0; j < 32; j++) {
            unsigned lo = __half_as_ushort(tb[(2 * j) * 264 + tid]);
            unsigned hi = __half_as_ushort(tb[(2 * j + 1) * 264 + tid]);
            ur[j] = lo | (hi << 16);
        }
        __half* dst = g_vthi + (size_t)tid * NK + m0;
#pragma unroll
        for (int j = 0; j < 8; j++) {
            uint4 v; v.x = ur[4 * j]; v.y = ur[4 * j + 1];
            v.z = ur[4 * j + 2]; v.w = ur[4 * j + 3];
            *(uint4*)(dst + 8 * j) = v;
        }
        return;
    }

    // modes 0 / 1: rope + fp16 store
    int nex = (mode == 1 && nex_ptr) ? *nex_ptr : 0;
    const int rope_limit = NK - nex;
    const int NN = (mode == 0) ? NQ : NK;
    __half* dsth = (mode == 0) ? g_qh : g_kh;

    float frv[8];
#pragma unroll
    for (int nt = 0; nt < 8; nt++) {
        int p = ((wc * 64 + nt * 8 + cc2) & 63) >> 1;
        frv[nt] = ex2(-(float)(p & 15) * 1.6609640474f);
    }

#pragma unroll
    for (int mt = 0; mt < 2; mt++)
#pragma unroll
        for (int rr = 0; rr < 2; rr++) {
            int m = m0 + wr * 32 + mt * 16 + r + rr * 8;
            bool dorope = (mode == 0) || (m < rope_limit);
            int pos = (mode == 0) ? m : (m & (NQ - 1));
            float tx = (float)(pos & 63), ty = (float)(pos >> 6);
#pragma unroll
            for (int nt = 0; nt < 8; nt++) {
                float v0 = cf[mt][nt][rr * 2] + b0v[nt];
                float v1 = cf[mt][nt][rr * 2 + 1] + b1v[nt];
                int n = wc * 64 + nt * 8 + cc2;
                int d = n & 63, h = n >> 6;
                if (dorope) {
                    int p = d >> 1;
                    float t = (p < 16) ? tx : ty;
                    float sn, cs;
                    __sincosf(t * frv[nt], &sn, &cs);
                    float x0 = v0;
                    v0 = x0 * cs - v1 * sn;
                    v1 = v1 * cs + x0 * sn;
                }
                if (mode == 0) { v0 *= 0.125f; v1 *= 0.125f; }
                *(unsigned*)&dsth[((size_t)h * NN + m) * 64 + d] = pkh(v1, v0);
            }
        }
}

// ---------------- HMMA flash attention (pure fp16 operands) ----------------
// Grid (16, HQ, KVS): CTA = 256 q rows x head x kv-slice(2048). 8 warps,
// warp owns 32 q rows (2 x m16). K/V tiles (128 kv) double-buffered.
// S phase: 2-stage software pipeline (QK MMAs of jp overlap exp of jp-1).
#define OKHI 0
#define OVHI 9216
#define BUFH 17920
#define SMEM_BYTES (2 * BUFH * 2)   // 71680

__device__ __forceinline__ void issue_tile(uint32_t sb, int buf, int kb,
    const __half* kh, const __half* vh, int tid)
{
    uint32_t base = sb + buf * (BUFH * 2);
#pragma unroll
    for (int i = 0; i < 4; i++) {
        int x = tid + i * 256;
        int krow = x >> 3, kch = x & 7;
        uint32_t kdst = base + (uint32_t)(krow * 72 + kch * 8) * 2;
        CP16(kdst + OKHI * 2, kh + (size_t)(kb + krow) * 64 + kch * 8);
        int vrow = x >> 4, vch = x & 15;
        uint32_t vdst = base + (uint32_t)(vrow * 136 + vch * 8) * 2;
        CP16(vdst + OVHI * 2, vh + (size_t)vrow * NK + kb + vch * 8);
    }
}

__global__ __launch_bounds__(256, 1) void attn_kernel()
{
    extern __shared__ char sm[];
    const uint32_t sb = smem_u32(sm);
    const int tid  = threadIdx.x;
    const int lane = tid & 31;
    const int w    = tid >> 5;
    const int qr   = w << 5;            // 32 q rows per warp
    const int h    = blockIdx.y;
    const int z    = blockIdx.z;        // kv slice
    const int n0   = blockIdx.x << 8;   // 256 q rows per CTA

    const int a_row = (lane & 7) + ((lane >> 3) & 1) * 8;
    const int a_k   = (lane >> 4) * 8;
    const int b_row = lane & 7;
    const int b_k   = (lane >> 3) * 8;

    {
        const __half* qhp = g_qh + ((size_t)h * NQ + n0) * 64;
        for (int x = tid; x < 2048; x += 256) {
            int row = x >> 3, ch = x & 7;
            *(uint4*)(sm + (row * 72 + ch * 8) * 2) =
                *(const uint4*)(qhp + row * 64 + ch * 8);
        }
    }
    __syncthreads();

    uint32_t qf[2][4][4];
#pragma unroll
    for (int m = 0; m < 2; m++)
#pragma unroll
        for (int ks = 0; ks < 4; ks++)
            LDX4(qf[m][ks], sb + (uint32_t)((qr + m * 16 + a_row) * 72 + ks * 16 + a_k) * 2);
    __syncthreads();

    float of[2][8][4];
#pragma unroll
    for (int m = 0; m < 2; m++)
#pragma unroll
        for (int n = 0; n < 8; n++)
#pragma unroll
            for (int e = 0; e < 4; e++) of[m][n][e] = 0.f;
    float rs[2][2] = {{0.f, 0.f}, {0.f, 0.f}};

    const __half* kh = g_kh + ((size_t)h * NK + (size_t)z * KVLEN) * 64;
    const __half* vh = g_vthi + (size_t)h * 64 * NK + (size_t)z * KVLEN;

    issue_tile(sb, 0, 0, kh, vh, tid);
    CPCOMMIT();

    for (int kt = 0; kt < KVLEN / 128; kt++) {
        if (kt < KVLEN / 128 - 1) {
            issue_tile(sb, (kt + 1) & 1, (kt + 1) * 128, kh, vh, tid);
            CPCOMMIT();
            CPWAIT(1);
        } else {
            CPWAIT(0);
        }
        __syncthreads();

        const uint32_t base = sb + (uint32_t)(kt & 1) * (BUFH * 2);

#pragma unroll
        for (int hv = 0; hv < 2; hv++) {
            float sfs[2][2][2][4];   // [stage][m][j-in-pair][e]
            uint32_t pf[2][4][4];

#pragma unroll
            for (int jp = 0; jp < 5; jp++) {
                if (jp < 4) {
                    float (*sc)[2][4] = sfs[jp & 1];
#pragma unroll
                    for (int m = 0; m < 2; m++)
#pragma unroll
                        for (int jj = 0; jj < 2; jj++)
#pragma unroll
                            for (int e = 0; e < 4; e++) sc[m][jj][e] = 0.f;

                    const int j0 = 2 * jp, j1 = 2 * jp + 1;
                    uint32_t bh0[8], bh1[8];
                    uint32_t ka0 = base + (uint32_t)((hv * 64 + j0 * 8 + b_row) * 72 + b_k) * 2;
                    uint32_t ka1 = base + (uint32_t)((hv * 64 + j1 * 8 + b_row) * 72 + b_k) * 2;
                    LDX4(bh0, ka0); LDX4(bh0 + 4, ka0 + 64);
                    LDX4(bh1, ka1); LDX4(bh1 + 4, ka1 + 64);
#pragma unroll
                    for (int ks = 0; ks < 4; ks++) {
                        MMAH(sc[0][0], qf[0][ks], bh0[2 * ks], bh0[2 * ks + 1]);
                        MMAH(sc[1][0], qf[1][ks], bh0[2 * ks], bh0[2 * ks + 1]);
                        MMAH(sc[0][1], qf[0][ks], bh1[2 * ks], bh1[2 * ks + 1]);
                        MMAH(sc[1][1], qf[1][ks], bh1[2 * ks], bh1[2 * ks + 1]);
                    }
                }
                if (jp > 0) {
                    float (*sp)[2][4] = sfs[(jp - 1) & 1];
                    const int kp = jp - 1;
#pragma unroll
                    for (int m = 0; m < 2; m++) {
                        float e00 = __expf(sp[m][0][0]);
                        float e01 = __expf(sp[m][0][1]);
                        float e02 = __expf(sp[m][0][2]);
                        float e03 = __expf(sp[m][0][3]);
                        float e10 = __expf(sp[m][1][0]);
                        float e11 = __expf(sp[m][1][1]);
                        float e12 = __expf(sp[m][1][2]);
                        float e13 = __expf(sp[m][1][3]);
                        rs[m][0] += e00 + e01 + e10 + e11;
                        rs[m][1] += e02 + e03 + e12 + e13;
                        pf[m][kp][0] = pkh(e01, e00);
                        pf[m][kp][1] = pkh(e03, e02);
                        pf[m][kp][2] = pkh(e11, e10);
                        pf[m][kp][3] = pkh(e13, e12);
                    }
                }
            }

#pragma unroll
            for (int np = 0; np < 4; np++) {
                const int d0 = 2 * np, d1 = 2 * np + 1;
                uint32_t vh0[8], vh1[8];
                uint32_t va0 = base + OVHI * 2 +
                               (uint32_t)((d0 * 8 + b_row) * 136 + hv * 64 + b_k) * 2;
                uint32_t va1 = base + OVHI * 2 +
                               (uint32_t)((d1 * 8 + b_row) * 136 + hv * 64 + b_k) * 2;
                LDX4(vh0, va0); LDX4(vh0 + 4, va0 + 64);
                LDX4(vh1, va1); LDX4(vh1 + 4, va1 + 64);
#pragma unroll
                for (int kp = 0; kp < 4; kp++) {
                    MMAH(of[0][d0], pf[0][kp], vh0[2 * kp], vh0[2 * kp + 1]);
                    MMAH(of[1][d0], pf[1][kp], vh0[2 * kp], vh0[2 * kp + 1]);
                    MMAH(of[0][d1], pf[0][kp], vh1[2 * kp], vh1[2 * kp + 1]);
                    MMAH(of[1][d1], pf[1][kp], vh1[2 * kp], vh1[2 * kp + 1]);
                }
            }
        }
        __syncthreads();
    }

#pragma unroll
    for (int m = 0; m < 2; m++)
#pragma unroll
        for (int rdx = 0; rdx < 2; rdx++) {
            rs[m][rdx] += __shfl_xor_sync(0xffffffffu, rs[m][rdx], 1);
            rs[m][rdx] += __shfl_xor_sync(0xffffffffu, rs[m][rdx], 2);
        }

    const int g = lane >> 2, tq = lane & 3;
    float* po = g_po + ((size_t)(z * HQ + h) * NQ + n0 + qr) * 64;
#pragma unroll
    for (int m = 0; m < 2; m++)
#pragma unroll
        for (int n = 0; n < 8; n++) {
            *(float2*)(po + (size_t)(m * 16 + g) * 64 + n * 8 + tq * 2) =
                make_float2(of[m][n][0], of[m][n][1]);
            *(float2*)(po + (size_t)(m * 16 + g + 8) * 64 + n * 8 + tq * 2) =
                make_float2(of[m][n][2], of[m][n][3]);
        }
    if (tq == 0) {
        float* pl = g_pl + (size_t)(z * HQ + h) * NQ + n0 + qr;
#pragma unroll
        for (int m = 0; m < 2; m++) {
            pl[m * 16 + g]     = rs[m][0];
            pl[m * 16 + g + 8] = rs[m][1];
        }
    }
}

// ---------------------------------------------------------------------------
extern "C" void kernel_launch(void* const* d_in, const int* in_sizes, int n_in,
                              void* d_out, int out_size)
{
    const float* query = (const float*)d_in[0];
    const float* key_  = (const float*)d_in[1];
    const float* value = (const float*)d_in[2];
    const float* Wq = (const float*)d_in[3];
    const float* bq = (const float*)d_in[4];
    const float* Wk = (const float*)d_in[5];
    const float* bk = (const float*)d_in[6];
    const float* Wv = (const float*)d_in[7];
    const float* bv = (const float*)d_in[8];
    const float* Wo = (const float*)d_in[9];
    const float* bo = (const float*)d_in[10];
    const int* nex = (n_in > 11) ? (const int*)d_in[11] : nullptr;
    float* out = (float*)d_out;

    cudaFuncSetAttribute(attn_kernel, cudaFuncAttributeMaxDynamicSharedMemorySize, SMEM_BYTES);
    cudaFuncSetAttribute(mm_kernel, cudaFuncAttributeMaxDynamicSharedMemorySize, PROJ_SMEM);

    mm_kernel<<<320, 256, PROJ_SMEM>>>(query, key_, value, Wq, bq, Wk, bk,
                                       Wv, bv, Wo, bo, nullptr, nex, 0);
    attn_kernel<<<dim3(NQ / 256, HQ, KVS), 256, SMEM_BYTES>>>();
    mm_kernel<<<64, 256, PROJ_SMEM>>>(query, key_, value, Wq, bq, Wk, bk,
                                      Wv, bv, Wo, bo, out, nullptr, 1);
}

// round 12
// speedup vs baseline: 1.1666x; 1.1666x over previous
#include <cuda_runtime.h>
#include <cuda_fp16.h>
#include <cstdint>

#define HQ 4
#define NQ 4096
#define NK 8192
#define KVS 4           // kv splits
#define KVLEN (NK / KVS)

// ---------------- scratch (allocation-free __device__ globals) -------------
__device__ __align__(16) __half g_qh [HQ * NQ * 64];    // q fp16 (rope'd, /8)
__device__ __align__(16) __half g_kh [HQ * NK * 64];    // k fp16 (rope'd)
__device__ __align__(16) __half g_vthi[HQ * 64 * NK];   // [h][d][n]
__device__ __align__(16) float g_po[KVS * HQ * NQ * 64]; // partial O (unnormalized)
__device__ __align__(16) float g_pl[KVS * HQ * NQ];      // partial row sums
// pre-transposed + fp16-split weights: W^T [n=256][K]
__device__ __align__(16) __half g_wqh[256 * 256], g_wql[256 * 256];
__device__ __align__(16) __half g_wkh[256 * 64],  g_wkl[256 * 64];
__device__ __align__(16) __half g_wvh[256 * 64],  g_wvl[256 * 64];
__device__ __align__(16) __half g_woh[256 * 256], g_wol[256 * 256];

// ---------------- helpers ---------------------------------------------------
__device__ __forceinline__ uint32_t smem_u32(const void* p) {
    uint32_t a;
    asm("{ .reg .u64 t; cvta.to.shared.u64 t, %1; cvt.u32.u64 %0, t; }" : "=r"(a) : "l"(p));
    return a;
}
__device__ __forceinline__ unsigned pkh(float hi, float lo) {
    unsigned r;
    asm("cvt.rn.f16x2.f32 %0, %1, %2;" : "=r"(r) : "f"(hi), "f"(lo));
    return r;
}
__device__ __forceinline__ float h_lo(unsigned p) {
    return __half2float(__ushort_as_half((unsigned short)(p & 0xffff)));
}
__device__ __forceinline__ float h_hi(unsigned p) {
    return __half2float(__ushort_as_half((unsigned short)(p >> 16)));
}
__device__ __forceinline__ float ex2(float x) {
    float r;
    asm("ex2.approx.f32 %0, %1;" : "=f"(r) : "f"(x));
    return r;
}

#define LDX4(r, a) asm volatile( \
    "ldmatrix.sync.aligned.m8n8.x4.shared.b16 {%0,%1,%2,%3}, [%4];" \
    : "=r"((r)[0]), "=r"((r)[1]), "=r"((r)[2]), "=r"((r)[3]) : "r"(a))

#define MMAH(c, a, b0, b1) asm volatile( \
    "mma.sync.aligned.m16n8k16.row.col.f32.f16.f16.f32 " \
    "{%0,%1,%2,%3},{%4,%5,%6,%7},{%8,%9},{%0,%1,%2,%3};" \
    : "+f"((c)[0]), "+f"((c)[1]), "+f"((c)[2]), "+f"((c)[3]) \
    : "r"((a)[0]), "r"((a)[1]), "r"((a)[2]), "r"((a)[3]), "r"(b0), "r"(b1))

#define CP16(dst, src) asm volatile( \
    "cp.async.cg.shared.global [%0], [%1], 16;" :: "r"(dst), "l"(src))
#define CPCOMMIT() asm volatile("cp.async.commit_group;" ::: "memory")
#define CPWAIT(n)  asm volatile("cp.async.wait_group %0;" :: "n"(n) : "memory")

// ---------------- weight prep: transpose + fp16 hi/lo split ----------------
// grid 160: bx<64 Wq, <80 Wk, <96 Wv, else Wo. One 32x32 tile per CTA.
__global__ void wprep_kernel(const float* __restrict__ Wq,
                             const float* __restrict__ Wk,
                             const float* __restrict__ Wv,
                             const float* __restrict__ Wo)
{
    __shared__ float t[32][33];
    int bx = blockIdx.x;
    const float* W; __half *dh, *dl; int Kw;
    if (bx < 64)      { W = Wq; dh = g_wqh; dl = g_wql; Kw = 256; }
    else if (bx < 80) { W = Wk; dh = g_wkh; dl = g_wkl; Kw = 64;  bx -= 64; }
    else if (bx < 96) { W = Wv; dh = g_wvh; dl = g_wvl; Kw = 64;  bx -= 80; }
    else              { W = Wo; dh = g_woh; dl = g_wol; Kw = 256; bx -= 96; }
    const int ntk = Kw >> 5;
    const int tk = (bx % ntk) << 5, tn = (bx / ntk) << 5;
    const int tid = threadIdx.x;
    {
        int kl = tid >> 3, nl4 = (tid & 7) * 4;
        float4 v = *(const float4*)&W[(size_t)(tk + kl) * 256 + tn + nl4];
        t[kl][nl4] = v.x; t[kl][nl4 + 1] = v.y;
        t[kl][nl4 + 2] = v.z; t[kl][nl4 + 3] = v.w;
    }
    __syncthreads();
    int nl = tid >> 3, kq = (tid & 7) * 4;
    unsigned short hv[4], lv[4];
#pragma unroll
    for (int i = 0; i < 4; i++) {
        float x = t[kq + i][nl];
        __half hb = __float2half_rn(x);
        hv[i] = __half_as_ushort(hb);
        lv[i] = __half_as_ushort(__float2half_rn(x - __half2float(hb)));
    }
    size_t o = (size_t)(tn + nl) * Kw + tk + kq;
    *(uint2*)&dh[o] = make_uint2(hv[0] | (hv[1] << 16), hv[2] | (hv[3] << 16));
    *(uint2*)&dl[o] = make_uint2(lv[0] | (lv[1] << 16), lv[2] | (lv[3] << 16));
}

// ---------------- fp16-split tensor-core projection GEMM -------------------
// CTA 64 rows x 256 cols, 8 warps (2x4, warp 32x64), chunk K=32, dbl-buffered.
// 3 products: a_hi*w_hi + a_hi*w_lo + a_lo*w_hi  (~fp32 accuracy).
// phase 0 (grid 320): bx<64 Q, <192 K, else V.  phase 1 (grid 64): O proj.
#define SA 40   // halfs per A row (32 + 8 pad)
#define SW 40
#define AOFF(buf, pl) ((buf) * 5120 + (pl) * 2560)
#define WOFF(buf, pl) (10240 + (buf) * 20480 + (pl) * 10240)
#define MM_SMEM (51200 * 2)   // 102400 bytes

__global__ __launch_bounds__(256, 1) void mm_kernel(
    const float* __restrict__ Aq, const float* __restrict__ Ak,
    const float* __restrict__ Av,
    const float* __restrict__ bq, const float* __restrict__ bk,
    const float* __restrict__ bv, const float* __restrict__ bo,
    float* __restrict__ outp, const int* __restrict__ nex_ptr, int phase)
{
    extern __shared__ __half smh[];
    __shared__ float linv[256];
    const uint32_t sb = smem_u32(smh);

    const int tid  = threadIdx.x;
    const int lane = tid & 31, w = tid >> 5;
    const int wr = w >> 2, wc = w & 3;
    const int r = lane >> 2, cl = lane & 3;
    const int a_row = (lane & 7) + ((lane >> 3) & 1) * 8;
    const int a_k   = (lane >> 4) * 8;
    const int b_row = lane & 7;
    const int b_k   = (lane >> 3) * 8;

    int mode, m0, Kd;
    const float *A = Aq, *bias;
    const __half *whi, *wlo;
    if (phase == 1) {
        mode = 3; m0 = blockIdx.x << 6; Kd = 256;
        whi = g_woh; wlo = g_wol; bias = bo;
    } else {
        int bx = blockIdx.x;
        if (bx < 64)       { mode = 0; m0 = bx << 6;         Kd = 256; A = Aq; whi = g_wqh; wlo = g_wql; bias = bq; }
        else if (bx < 192) { mode = 1; m0 = (bx - 64) << 6;  Kd = 64;  A = Ak; whi = g_wkh; wlo = g_wkl; bias = bk; }
        else               { mode = 2; m0 = (bx - 192) << 6; Kd = 64;  A = Av; whi = g_wvh; wlo = g_wvl; bias = bv; }
    }

    if (mode == 3) {
        int hh = tid >> 6, rl = tid & 63;
        float l = 0.f;
#pragma unroll
        for (int z = 0; z < KVS; z++)
            l += g_pl[(size_t)(z * HQ + hh) * NQ + m0 + rl];
        linv[tid] = 1.0f / l;
        __syncthreads();
    }

    const int NCH = Kd >> 5;
    const int arow = tid >> 2, acq = tid & 3;
    float4 ra0, ra1;

    auto ldgA = [&](int kc) {
        int k0 = kc + acq * 8;
        if (mode != 3) {
            ra0 = *(const float4*)&A[(size_t)(m0 + arow) * Kd + k0];
            ra1 = *(const float4*)&A[(size_t)(m0 + arow) * Kd + k0 + 4];
        } else {
            int hh = k0 >> 6, d = k0 & 63;
            size_t base = ((size_t)hh * NQ + m0 + arow) * 64 + d;
            float4 s0 = *(const float4*)&g_po[base];
            float4 s1 = *(const float4*)&g_po[base + 4];
#pragma unroll
            for (int z = 1; z < KVS; z++) {
                float4 p0 = *(const float4*)&g_po[(size_t)z * (HQ * NQ * 64) + base];
                float4 p1 = *(const float4*)&g_po[(size_t)z * (HQ * NQ * 64) + base + 4];
                s0.x += p0.x; s0.y += p0.y; s0.z += p0.z; s0.w += p0.w;
                s1.x += p1.x; s1.y += p1.y; s1.z += p1.z; s1.w += p1.w;
            }
            float iv = linv[hh * 64 + arow];
            ra0 = make_float4(s0.x * iv, s0.y * iv, s0.z * iv, s0.w * iv);
            ra1 = make_float4(s1.x * iv, s1.y * iv, s1.z * iv, s1.w * iv);
        }
    };

    auto stsA = [&](int buf) {
        unsigned h01 = pkh(ra0.y, ra0.x), h23 = pkh(ra0.w, ra0.z);
        unsigned h45 = pkh(ra1.y, ra1.x), h67 = pkh(ra1.w, ra1.z);
        unsigned l01 = pkh(ra0.y - h_hi(h01), ra0.x - h_lo(h01));
        unsigned l23 = pkh(ra0.w - h_hi(h23), ra0.z - h_lo(h23));
        unsigned l45 = pkh(ra1.y - h_hi(h45), ra1.x - h_lo(h45));
        unsigned l67 = pkh(ra1.w - h_hi(h67), ra1.z - h_lo(h67));
        int off = arow * SA + acq * 8;
        unsigned* ph = (unsigned*)&smh[AOFF(buf, 0) + off];
        ph[0] = h01; ph[1] = h23; ph[2] = h45; ph[3] = h67;
        unsigned* pl = (unsigned*)&smh[AOFF(buf, 1) + off];
        pl[0] = l01; pl[1] = l23; pl[2] = l45; pl[3] = l67;
    };

    auto cpW = [&](int kc, int buf) {
#pragma unroll
        for (int i = 0; i < 4; i++) {
            int idx = i * 256 + tid;
            int row = idx >> 2, seg = idx & 3;
            uint32_t d0 = sb + (uint32_t)(WOFF(buf, 0) + row * SW + seg * 8) * 2;
            uint32_t d1 = sb + (uint32_t)(WOFF(buf, 1) + row * SW + seg * 8) * 2;
            size_t so = (size_t)row * Kd + kc + seg * 8;
            CP16(d0, whi + so);
            CP16(d1, wlo + so);
        }
    };

    float cf[2][8][4];
#pragma unroll
    for (int mt = 0; mt < 2; mt++)
#pragma unroll
        for (int nt = 0; nt < 8; nt++)
#pragma unroll
            for (int e = 0; e < 4; e++) cf[mt][nt][e] = 0.f;

    ldgA(0); cpW(0, 0); CPCOMMIT();
    stsA(0);
    CPWAIT(0);
    __syncthreads();

    for (int ch = 0; ch < NCH; ch++) {
        if (ch + 1 < NCH) { ldgA((ch + 1) << 5); cpW((ch + 1) << 5, (ch + 1) & 1); CPCOMMIT(); }

        const int buf = ch & 1;
        uint32_t af[2][2][2][4];   // [plane][mt][ks]
#pragma unroll
        for (int mt = 0; mt < 2; mt++)
#pragma unroll
            for (int ks = 0; ks < 2; ks++) {
                uint32_t aa = sb + (uint32_t)((wr * 32 + mt * 16 + a_row) * SA + ks * 16 + a_k) * 2;
                LDX4(af[0][mt][ks], aa + AOFF(buf, 0) * 2);
                LDX4(af[1][mt][ks], aa + AOFF(buf, 1) * 2);
            }
#pragma unroll
        for (int nt = 0; nt < 8; nt++) {
            uint32_t bh[4], bl[4];
            uint32_t wa = sb + (uint32_t)(WOFF(buf, 0) + (wc * 64 + nt * 8 + b_row) * SW + b_k) * 2;
            LDX4(bh, wa);
            LDX4(bl, wa + 10240 * 2);
#pragma unroll
            for (int ks = 0; ks < 2; ks++) {
                MMAH(cf[0][nt], af[0][0][ks], bh[2 * ks], bh[2 * ks + 1]);
                MMAH(cf[1][nt], af[0][1][ks], bh[2 * ks], bh[2 * ks + 1]);
                MMAH(cf[0][nt], af[0][0][ks], bl[2 * ks], bl[2 * ks + 1]);
                MMAH(cf[1][nt], af[0][1][ks], bl[2 * ks], bl[2 * ks + 1]);
                MMAH(cf[0][nt], af[1][0][ks], bh[2 * ks], bh[2 * ks + 1]);
                MMAH(cf[1][nt], af[1][1][ks], bh[2 * ks], bh[2 * ks + 1]);
            }
        }

        if (ch + 1 < NCH) { stsA((ch + 1) & 1); CPWAIT(0); }
        __syncthreads();
    }

    // ---- epilogues ----
    const int cc2 = cl * 2;
    float b0v[8], b1v[8];
#pragma unroll
    for (int nt = 0; nt < 8; nt++) {
        int n = wc * 64 + nt * 8 + cc2;
        b0v[nt] = bias[n];
        b1v[nt] = bias[n + 1];
    }

    if (mode == 3) {
#pragma unroll
        for (int mt = 0; mt < 2; mt++)
#pragma unroll
            for (int rr = 0; rr < 2; rr++) {
                int row = m0 + wr * 32 + mt * 16 + r + rr * 8;
#pragma unroll
                for (int nt = 0; nt < 8; nt++) {
                    int n = wc * 64 + nt * 8 + cc2;
                    *(float2*)&outp[(size_t)row * 256 + n] = make_float2(
                        cf[mt][nt][rr * 2] + b0v[nt],
                        cf[mt][nt][rr * 2 + 1] + b1v[nt]);
                }
            }
        return;
    }

    if (mode == 2) {
        __half* tb = smh;   // [64][264]
#pragma unroll
        for (int mt = 0; mt < 2; mt++)
#pragma unroll
            for (int rr = 0; rr < 2; rr++) {
                int rowl = wr * 32 + mt * 16 + r + rr * 8;
#pragma unroll
                for (int nt = 0; nt < 8; nt++) {
                    int n = wc * 64 + nt * 8 + cc2;
                    *(unsigned*)&tb[rowl * 264 + n] = pkh(
                        cf[mt][nt][rr * 2 + 1] + b1v[nt],
                        cf[mt][nt][rr * 2] + b0v[nt]);
                }
            }
        __syncthreads();
        unsigned ur[32];
#pragma unroll
        for (int j = 0; j < 32; j++) {
            unsigned lo = __half_as_ushort(tb[(2 * j) * 264 + tid]);
            unsigned hi = __half_as_ushort(tb[(2 * j + 1) * 264 + tid]);
            ur[j] = lo | (hi << 16);
        }
        __half* dst = g_vthi + (size_t)tid * NK + m0;
#pragma unroll
        for (int j = 0; j < 8; j++) {
            uint4 v; v.x = ur[4 * j]; v.y = ur[4 * j + 1];
            v.z = ur[4 * j + 2]; v.w = ur[4 * j + 3];
            *(uint4*)(dst + 8 * j) = v;
        }
        return;
    }

    // modes 0 / 1: rope + fp16 store
    int nex = (mode == 1 && nex_ptr) ? *nex_ptr : 0;
    const int rope_limit = NK - nex;
    const int NN = (mode == 0) ? NQ : NK;
    __half* dsth = (mode == 0) ? g_qh : g_kh;

    float frv[8];
#pragma unroll
    for (int nt = 0; nt < 8; nt++) {
        int p = ((wc * 64 + nt * 8 + cc2) & 63) >> 1;
        frv[nt] = ex2(-(float)(p & 15) * 1.6609640474f);
    }

#pragma unroll
    for (int mt = 0; mt < 2; mt++)
#pragma unroll
        for (int rr = 0; rr < 2; rr++) {
            int m = m0 + wr * 32 + mt * 16 + r + rr * 8;
            bool dorope = (mode == 0) || (m < rope_limit);
            int pos = (mode == 0) ? m : (m & (NQ - 1));
            float tx = (float)(pos & 63), ty = (float)(pos >> 6);
#pragma unroll
            for (int nt = 0; nt < 8; nt++) {
                float v0 = cf[mt][nt][rr * 2] + b0v[nt];
                float v1 = cf[mt][nt][rr * 2 + 1] + b1v[nt];
                int n = wc * 64 + nt * 8 + cc2;
                int d = n & 63, h = n >> 6;
                if (dorope) {
                    int p = d >> 1;
                    float t = (p < 16) ? tx : ty;
                    float sn, cs;
                    __sincosf(t * frv[nt], &sn, &cs);
                    float x0 = v0;
                    v0 = x0 * cs - v1 * sn;
                    v1 = v1 * cs + x0 * sn;
                }
                if (mode == 0) { v0 *= 0.125f; v1 *= 0.125f; }
                *(unsigned*)&dsth[((size_t)h * NN + m) * 64 + d] = pkh(v1, v0);
            }
        }
}

// ---------------- HMMA flash attention (unchanged from round 10) -----------
#define OKHI 0
#define OVHI 9216
#define BUFH 17920
#define SMEM_BYTES (2 * BUFH * 2)   // 71680

__device__ __forceinline__ void issue_tile(uint32_t sb, int buf, int kb,
    const __half* kh, const __half* vh, int tid)
{
    uint32_t base = sb + buf * (BUFH * 2);
#pragma unroll
    for (int i = 0; i < 4; i++) {
        int x = tid + i * 256;
        int krow = x >> 3, kch = x & 7;
        uint32_t kdst = base + (uint32_t)(krow * 72 + kch * 8) * 2;
        CP16(kdst + OKHI * 2, kh + (size_t)(kb + krow) * 64 + kch * 8);
        int vrow = x >> 4, vch = x & 15;
        uint32_t vdst = base + (uint32_t)(vrow * 136 + vch * 8) * 2;
        CP16(vdst + OVHI * 2, vh + (size_t)vrow * NK + kb + vch * 8);
    }
}

__global__ __launch_bounds__(256, 1) void attn_kernel()
{
    extern __shared__ char sm[];
    const uint32_t sb = smem_u32(sm);
    const int tid  = threadIdx.x;
    const int lane = tid & 31;
    const int w    = tid >> 5;
    const int qr   = w << 5;
    const int h    = blockIdx.y;
    const int z    = blockIdx.z;
    const int n0   = blockIdx.x << 8;

    const int a_row = (lane & 7) + ((lane >> 3) & 1) * 8;
    const int a_k   = (lane >> 4) * 8;
    const int b_row = lane & 7;
    const int b_k   = (lane >> 3) * 8;

    {
        const __half* qhp = g_qh + ((size_t)h * NQ + n0) * 64;
        for (int x = tid; x < 2048; x += 256) {
            int row = x >> 3, ch = x & 7;
            *(uint4*)(sm + (row * 72 + ch * 8) * 2) =
                *(const uint4*)(qhp + row * 64 + ch * 8);
        }
    }
    __syncthreads();

    uint32_t qf[2][4][4];
#pragma unroll
    for (int m = 0; m < 2; m++)
#pragma unroll
        for (int ks = 0; ks < 4; ks++)
            LDX4(qf[m][ks], sb + (uint32_t)((qr + m * 16 + a_row) * 72 + ks * 16 + a_k) * 2);
    __syncthreads();

    float of[2][8][4];
#pragma unroll
    for (int m = 0; m < 2; m++)
#pragma unroll
        for (int n = 0; n < 8; n++)
#pragma unroll
            for (int e = 0; e < 4; e++) of[m][n][e] = 0.f;
    float rs[2][2] = {{0.f, 0.f}, {0.f, 0.f}};

    const __half* kh = g_kh + ((size_t)h * NK + (size_t)z * KVLEN) * 64;
    const __half* vh = g_vthi + (size_t)h * 64 * NK + (size_t)z * KVLEN;

    issue_tile(sb, 0, 0, kh, vh, tid);
    CPCOMMIT();

    for (int kt = 0; kt < KVLEN / 128; kt++) {
        if (kt < KVLEN / 128 - 1) {
            issue_tile(sb, (kt + 1) & 1, (kt + 1) * 128, kh, vh, tid);
            CPCOMMIT();
            CPWAIT(1);
        } else {
            CPWAIT(0);
        }
        __syncthreads();

        const uint32_t base = sb + (uint32_t)(kt & 1) * (BUFH * 2);

#pragma unroll
        for (int hv = 0; hv < 2; hv++) {
            float sfs[2][2][2][4];
            uint32_t pf[2][4][4];

#pragma unroll
            for (int jp = 0; jp < 5; jp++) {
                if (jp < 4) {
                    float (*sc)[2][4] = sfs[jp & 1];
#pragma unroll
                    for (int m = 0; m < 2; m++)
#pragma unroll
                        for (int jj = 0; jj < 2; jj++)
#pragma unroll
                            for (int e = 0; e < 4; e++) sc[m][jj][e] = 0.f;

                    const int j0 = 2 * jp, j1 = 2 * jp + 1;
                    uint32_t bh0[8], bh1[8];
                    uint32_t ka0 = base + (uint32_t)((hv * 64 + j0 * 8 + b_row) * 72 + b_k) * 2;
                    uint32_t ka1 = base + (uint32_t)((hv * 64 + j1 * 8 + b_row) * 72 + b_k) * 2;
                    LDX4(bh0, ka0); LDX4(bh0 + 4, ka0 + 64);
                    LDX4(bh1, ka1); LDX4(bh1 + 4, ka1 + 64);
#pragma unroll
                    for (int ks = 0; ks < 4; ks++) {
                        MMAH(sc[0][0], qf[0][ks], bh0[2 * ks], bh0[2 * ks + 1]);
                        MMAH(sc[1][0], qf[1][ks], bh0[2 * ks], bh0[2 * ks + 1]);
                        MMAH(sc[0][1], qf[0][ks], bh1[2 * ks], bh1[2 * ks + 1]);
                        MMAH(sc[1][1], qf[1][ks], bh1[2 * ks], bh1[2 * ks + 1]);
                    }
                }
                if (jp > 0) {
                    float (*sp)[2][4] = sfs[(jp - 1) & 1];
                    const int kp = jp - 1;
#pragma unroll
                    for (int m = 0; m < 2; m++) {
                        float e00 = __expf(sp[m][0][0]);
                        float e01 = __expf(sp[m][0][1]);
                        float e02 = __expf(sp[m][0][2]);
                        float e03 = __expf(sp[m][0][3]);
                        float e10 = __expf(sp[m][1][0]);
                        float e11 = __expf(sp[m][1][1]);
                        float e12 = __expf(sp[m][1][2]);
                        float e13 = __expf(sp[m][1][3]);
                        rs[m][0] += e00 + e01 + e10 + e11;
                        rs[m][1] += e02 + e03 + e12 + e13;
                        pf[m][kp][0] = pkh(e01, e00);
                        pf[m][kp][1] = pkh(e03, e02);
                        pf[m][kp][2] = pkh(e11, e10);
                        pf[m][kp][3] = pkh(e13, e12);
                    }
                }
            }

#pragma unroll
            for (int np = 0; np < 4; np++) {
                const int d0 = 2 * np, d1 = 2 * np + 1;
                uint32_t vh0[8], vh1[8];
                uint32_t va0 = base + OVHI * 2 +
                               (uint32_t)((d0 * 8 + b_row) * 136 + hv * 64 + b_k) * 2;
                uint32_t va1 = base + OVHI * 2 +
                               (uint32_t)((d1 * 8 + b_row) * 136 + hv * 64 + b_k) * 2;
                LDX4(vh0, va0); LDX4(vh0 + 4, va0 + 64);
                LDX4(vh1, va1); LDX4(vh1 + 4, va1 + 64);
#pragma unroll
                for (int kp = 0; kp < 4; kp++) {
                    MMAH(of[0][d0], pf[0][kp], vh0[2 * kp], vh0[2 * kp + 1]);
                    MMAH(of[1][d0], pf[1][kp], vh0[2 * kp], vh0[2 * kp + 1]);
                    MMAH(of[0][d1], pf[0][kp], vh1[2 * kp], vh1[2 * kp + 1]);
                    MMAH(of[1][d1], pf[1][kp], vh1[2 * kp], vh1[2 * kp + 1]);
                }
            }
        }
        __syncthreads();
    }

#pragma unroll
    for (int m = 0; m < 2; m++)
#pragma unroll
        for (int rdx = 0; rdx < 2; rdx++) {
            rs[m][rdx] += __shfl_xor_sync(0xffffffffu, rs[m][rdx], 1);
            rs[m][rdx] += __shfl_xor_sync(0xffffffffu, rs[m][rdx], 2);
        }

    const int g = lane >> 2, tq = lane & 3;
    float* po = g_po + ((size_t)(z * HQ + h) * NQ + n0 + qr) * 64;
#pragma unroll
    for (int m = 0; m < 2; m++)
#pragma unroll
        for (int n = 0; n < 8; n++) {
            *(float2*)(po + (size_t)(m * 16 + g) * 64 + n * 8 + tq * 2) =
                make_float2(of[m][n][0], of[m][n][1]);
            *(float2*)(po + (size_t)(m * 16 + g + 8) * 64 + n * 8 + tq * 2) =
                make_float2(of[m][n][2], of[m][n][3]);
        }
    if (tq == 0) {
        float* pl = g_pl + (size_t)(z * HQ + h) * NQ + n0 + qr;
#pragma unroll
        for (int m = 0; m < 2; m++) {
            pl[m * 16 + g]     = rs[m][0];
            pl[m * 16 + g + 8] = rs[m][1];
        }
    }
}

// ---------------------------------------------------------------------------
extern "C" void kernel_launch(void* const* d_in, const int* in_sizes, int n_in,
                              void* d_out, int out_size)
{
    const float* query = (const float*)d_in[0];
    const float* key_  = (const float*)d_in[1];
    const float* value = (const float*)d_in[2];
    const float* Wq = (const float*)d_in[3];
    const float* bq = (const float*)d_in[4];
    const float* Wk = (const float*)d_in[5];
    const float* bk = (const float*)d_in[6];
    const float* Wv = (const float*)d_in[7];
    const float* bv = (const float*)d_in[8];
    const float* Wo = (const float*)d_in[9];
    const float* bo = (const float*)d_in[10];
    const int* nex = (n_in > 11) ? (const int*)d_in[11] : nullptr;
    float* out = (float*)d_out;

    cudaFuncSetAttribute(attn_kernel, cudaFuncAttributeMaxDynamicSharedMemorySize, SMEM_BYTES);
    cudaFuncSetAttribute(mm_kernel, cudaFuncAttributeMaxDynamicSharedMemorySize, MM_SMEM);

    wprep_kernel<<<160, 256>>>(Wq, Wk, Wv, Wo);
    mm_kernel<<<320, 256, MM_SMEM>>>(query, key_, value, bq, bk, bv, bo,
                                     nullptr, nex, 0);
    attn_kernel<<<dim3(NQ / 256, HQ, KVS), 256, SMEM_BYTES>>>();
    mm_kernel<<<64, 256, MM_SMEM>>>(query, key_, value, bq, bk, bv, bo,
                                    out, nullptr, 1);
}

// round 13
// speedup vs baseline: 1.2147x; 1.0412x over previous
#include <cuda_runtime.h>
#include <cuda_fp16.h>
#include <cstdint>

#define HQ 4
#define NQ 4096
#define NK 8192
#define KVS 4           // kv splits
#define KVLEN (NK / KVS)

// ---------------- scratch (allocation-free __device__ globals) -------------
__device__ __align__(16) __half g_qh [HQ * NQ * 64];    // q fp16 (rope'd, /8)
__device__ __align__(16) __half g_kh [HQ * NK * 64];    // k fp16 (rope'd)
__device__ __align__(16) __half g_vthi[HQ * 64 * NK];   // [h][d][n]
__device__ __align__(16) __half g_poh[KVS * HQ * NQ * 64]; // partial O (fp16)
__device__ __align__(16) float g_pl[KVS * HQ * NQ];      // partial row sums
// pre-transposed + fp16-split weights: W^T [n=256][K]
__device__ __align__(16) __half g_wqh[256 * 256], g_wql[256 * 256];
__device__ __align__(16) __half g_wkh[256 * 64],  g_wkl[256 * 64];
__device__ __align__(16) __half g_wvh[256 * 64],  g_wvl[256 * 64];
__device__ __align__(16) __half g_woh[256 * 256], g_wol[256 * 256];

// ---------------- helpers ---------------------------------------------------
__device__ __forceinline__ uint32_t smem_u32(const void* p) {
    uint32_t a;
    asm("{ .reg .u64 t; cvta.to.shared.u64 t, %1; cvt.u32.u64 %0, t; }" : "=r"(a) : "l"(p));
    return a;
}
__device__ __forceinline__ unsigned pkh(float hi, float lo) {
    unsigned r;
    asm("cvt.rn.f16x2.f32 %0, %1, %2;" : "=r"(r) : "f"(hi), "f"(lo));
    return r;
}
__device__ __forceinline__ float h_lo(unsigned p) {
    return __half2float(__ushort_as_half((unsigned short)(p & 0xffff)));
}
__device__ __forceinline__ float h_hi(unsigned p) {
    return __half2float(__ushort_as_half((unsigned short)(p >> 16)));
}
__device__ __forceinline__ float ex2(float x) {
    float r;
    asm("ex2.approx.f32 %0, %1;" : "=f"(r) : "f"(x));
    return r;
}

#define LDX4(r, a) asm volatile( \
    "ldmatrix.sync.aligned.m8n8.x4.shared.b16 {%0,%1,%2,%3}, [%4];" \
    : "=r"((r)[0]), "=r"((r)[1]), "=r"((r)[2]), "=r"((r)[3]) : "r"(a))

#define MMAH(c, a, b0, b1) asm volatile( \
    "mma.sync.aligned.m16n8k16.row.col.f32.f16.f16.f32 " \
    "{%0,%1,%2,%3},{%4,%5,%6,%7},{%8,%9},{%0,%1,%2,%3};" \
    : "+f"((c)[0]), "+f"((c)[1]), "+f"((c)[2]), "+f"((c)[3]) \
    : "r"((a)[0]), "r"((a)[1]), "r"((a)[2]), "r"((a)[3]), "r"(b0), "r"(b1))

#define CP16(dst, src) asm volatile( \
    "cp.async.cg.shared.global [%0], [%1], 16;" :: "r"(dst), "l"(src))
#define CPCOMMIT() asm volatile("cp.async.commit_group;" ::: "memory")
#define CPWAIT(n)  asm volatile("cp.async.wait_group %0;" :: "n"(n) : "memory")

// ---------------- weight prep: transpose + fp16 hi/lo split ----------------
__global__ void wprep_kernel(const float* __restrict__ Wq,
                             const float* __restrict__ Wk,
                             const float* __restrict__ Wv,
                             const float* __restrict__ Wo)
{
    __shared__ float t[32][33];
    int bx = blockIdx.x;
    const float* W; __half *dh, *dl; int Kw;
    if (bx < 64)      { W = Wq; dh = g_wqh; dl = g_wql; Kw = 256; }
    else if (bx < 80) { W = Wk; dh = g_wkh; dl = g_wkl; Kw = 64;  bx -= 64; }
    else if (bx < 96) { W = Wv; dh = g_wvh; dl = g_wvl; Kw = 64;  bx -= 80; }
    else              { W = Wo; dh = g_woh; dl = g_wol; Kw = 256; bx -= 96; }
    const int ntk = Kw >> 5;
    const int tk = (bx % ntk) << 5, tn = (bx / ntk) << 5;
    const int tid = threadIdx.x;
    {
        int kl = tid >> 3, nl4 = (tid & 7) * 4;
        float4 v = *(const float4*)&W[(size_t)(tk + kl) * 256 + tn + nl4];
        t[kl][nl4] = v.x; t[kl][nl4 + 1] = v.y;
        t[kl][nl4 + 2] = v.z; t[kl][nl4 + 3] = v.w;
    }
    __syncthreads();
    int nl = tid >> 3, kq = (tid & 7) * 4;
    unsigned short hv[4], lv[4];
#pragma unroll
    for (int i = 0; i < 4; i++) {
        float x = t[kq + i][nl];
        __half hb = __float2half_rn(x);
        hv[i] = __half_as_ushort(hb);
        lv[i] = __half_as_ushort(__float2half_rn(x - __half2float(hb)));
    }
    size_t o = (size_t)(tn + nl) * Kw + tk + kq;
    *(uint2*)&dh[o] = make_uint2(hv[0] | (hv[1] << 16), hv[2] | (hv[3] << 16));
    *(uint2*)&dl[o] = make_uint2(lv[0] | (lv[1] << 16), lv[2] | (lv[3] << 16));
}

// ---------------- fp16-split tensor-core projection GEMM -------------------
// PH=0, grid 320: bx<64 Q, <192 K, else V. 64 rows x 256 cols per CTA.
// PH=1, grid (64,2): O proj. 64 rows x 128 cols per CTA (n split halves).
#define SA 40
#define SW 40
#define AOFF(buf, pl) ((buf) * 5120 + (pl) * 2560)
#define WOFF(buf, pl) (10240 + (buf) * 20480 + (pl) * 10240)
#define MM_SMEM (51200 * 2)

template <int PH>
__global__ __launch_bounds__(256, 1) void mm_kernel(
    const float* __restrict__ Aq, const float* __restrict__ Ak,
    const float* __restrict__ Av,
    const float* __restrict__ bq, const float* __restrict__ bk,
    const float* __restrict__ bv, const float* __restrict__ bo,
    float* __restrict__ outp, const int* __restrict__ nex_ptr)
{
    extern __shared__ __half smh[];
    __shared__ float linv[256];
    const uint32_t sb = smem_u32(smh);

    constexpr int NT = PH ? 4 : 8;        // n-tiles per warp
    constexpr int NWC = PH ? 32 : 64;     // cols per warp

    const int tid  = threadIdx.x;
    const int lane = tid & 31, w = tid >> 5;
    const int wr = w >> 2, wc = w & 3;
    const int r = lane >> 2, cl = lane & 3;
    const int a_row = (lane & 7) + ((lane >> 3) & 1) * 8;
    const int a_k   = (lane >> 4) * 8;
    const int b_row = lane & 7;
    const int b_k   = (lane >> 3) * 8;
    const int nbase = PH ? (blockIdx.y << 7) : 0;
    const int ncols = PH ? 128 : 256;

    int mode, m0, Kd;
    const float *A = Aq, *bias;
    const __half *whi, *wlo;
    if (PH) {
        mode = 3; m0 = blockIdx.x << 6; Kd = 256;
        whi = g_woh; wlo = g_wol; bias = bo;
    } else {
        int bx = blockIdx.x;
        if (bx < 64)       { mode = 0; m0 = bx << 6;         Kd = 256; A = Aq; whi = g_wqh; wlo = g_wql; bias = bq; }
        else if (bx < 192) { mode = 1; m0 = (bx - 64) << 6;  Kd = 64;  A = Ak; whi = g_wkh; wlo = g_wkl; bias = bk; }
        else               { mode = 2; m0 = (bx - 192) << 6; Kd = 64;  A = Av; whi = g_wvh; wlo = g_wvl; bias = bv; }
    }

    if (PH) {
        int hh = tid >> 6, rl = tid & 63;
        float l = 0.f;
#pragma unroll
        for (int z = 0; z < KVS; z++)
            l += g_pl[(size_t)(z * HQ + hh) * NQ + m0 + rl];
        linv[tid] = 1.0f / l;
        __syncthreads();
    }

    const int NCH = Kd >> 5;
    const int arow = tid >> 2, acq = tid & 3;
    float4 ra0, ra1;

    auto ldgA = [&](int kc) {
        int k0 = kc + acq * 8;
        if (!PH) {
            ra0 = *(const float4*)&A[(size_t)(m0 + arow) * Kd + k0];
            ra1 = *(const float4*)&A[(size_t)(m0 + arow) * Kd + k0 + 4];
        } else {
            int hh = k0 >> 6, d = k0 & 63;
            size_t base = ((size_t)hh * NQ + m0 + arow) * 64 + d;
            uint4 v = *(const uint4*)&g_poh[base];
            __half2 s0 = *(__half2*)&v.x, s1 = *(__half2*)&v.y;
            __half2 s2 = *(__half2*)&v.z, s3 = *(__half2*)&v.w;
#pragma unroll
            for (int z = 1; z < KVS; z++) {
                uint4 p = *(const uint4*)&g_poh[(size_t)z * (HQ * NQ * 64) + base];
                s0 = __hadd2(s0, *(__half2*)&p.x);
                s1 = __hadd2(s1, *(__half2*)&p.y);
                s2 = __hadd2(s2, *(__half2*)&p.z);
                s3 = __hadd2(s3, *(__half2*)&p.w);
            }
            float iv = linv[hh * 64 + arow];
            ra0 = make_float4(__low2float(s0) * iv, __high2float(s0) * iv,
                              __low2float(s1) * iv, __high2float(s1) * iv);
            ra1 = make_float4(__low2float(s2) * iv, __high2float(s2) * iv,
                              __low2float(s3) * iv, __high2float(s3) * iv);
        }
    };

    auto stsA = [&](int buf) {
        unsigned h01 = pkh(ra0.y, ra0.x), h23 = pkh(ra0.w, ra0.z);
        unsigned h45 = pkh(ra1.y, ra1.x), h67 = pkh(ra1.w, ra1.z);
        unsigned l01 = pkh(ra0.y - h_hi(h01), ra0.x - h_lo(h01));
        unsigned l23 = pkh(ra0.w - h_hi(h23), ra0.z - h_lo(h23));
        unsigned l45 = pkh(ra1.y - h_hi(h45), ra1.x - h_lo(h45));
        unsigned l67 = pkh(ra1.w - h_hi(h67), ra1.z - h_lo(h67));
        int off = arow * SA + acq * 8;
        unsigned* ph = (unsigned*)&smh[AOFF(buf, 0) + off];
        ph[0] = h01; ph[1] = h23; ph[2] = h45; ph[3] = h67;
        unsigned* pl = (unsigned*)&smh[AOFF(buf, 1) + off];
        pl[0] = l01; pl[1] = l23; pl[2] = l45; pl[3] = l67;
    };

    auto cpW = [&](int kc, int buf) {
        const int NIT = PH ? 2 : 4;
#pragma unroll
        for (int i = 0; i < NIT; i++) {
            int idx = i * 256 + tid;
            int row = idx >> 2, seg = idx & 3;
            uint32_t d0 = sb + (uint32_t)(WOFF(buf, 0) + row * SW + seg * 8) * 2;
            uint32_t d1 = sb + (uint32_t)(WOFF(buf, 1) + row * SW + seg * 8) * 2;
            size_t so = (size_t)(nbase + row) * Kd + kc + seg * 8;
            CP16(d0, whi + so);
            CP16(d1, wlo + so);
        }
    };

    float cf[2][NT][4];
#pragma unroll
    for (int mt = 0; mt < 2; mt++)
#pragma unroll
        for (int nt = 0; nt < NT; nt++)
#pragma unroll
            for (int e = 0; e < 4; e++) cf[mt][nt][e] = 0.f;

    ldgA(0); cpW(0, 0); CPCOMMIT();
    stsA(0);
    CPWAIT(0);
    __syncthreads();

    for (int ch = 0; ch < NCH; ch++) {
        if (ch + 1 < NCH) { ldgA((ch + 1) << 5); cpW((ch + 1) << 5, (ch + 1) & 1); CPCOMMIT(); }

        const int buf = ch & 1;
        uint32_t af[2][2][2][4];
#pragma unroll
        for (int mt = 0; mt < 2; mt++)
#pragma unroll
            for (int ks = 0; ks < 2; ks++) {
                uint32_t aa = sb + (uint32_t)((wr * 32 + mt * 16 + a_row) * SA + ks * 16 + a_k) * 2;
                LDX4(af[0][mt][ks], aa + AOFF(buf, 0) * 2);
                LDX4(af[1][mt][ks], aa + AOFF(buf, 1) * 2);
            }
#pragma unroll
        for (int nt = 0; nt < NT; nt++) {
            uint32_t bh[4], bl[4];
            uint32_t wa = sb + (uint32_t)(WOFF(buf, 0) + (wc * NWC + nt * 8 + b_row) * SW + b_k) * 2;
            LDX4(bh, wa);
            LDX4(bl, wa + 10240 * 2);
#pragma unroll
            for (int ks = 0; ks < 2; ks++) {
                MMAH(cf[0][nt], af[0][0][ks], bh[2 * ks], bh[2 * ks + 1]);
                MMAH(cf[1][nt], af[0][1][ks], bh[2 * ks], bh[2 * ks + 1]);
                MMAH(cf[0][nt], af[0][0][ks], bl[2 * ks], bl[2 * ks + 1]);
                MMAH(cf[1][nt], af[0][1][ks], bl[2 * ks], bl[2 * ks + 1]);
                MMAH(cf[0][nt], af[1][0][ks], bh[2 * ks], bh[2 * ks + 1]);
                MMAH(cf[1][nt], af[1][1][ks], bh[2 * ks], bh[2 * ks + 1]);
            }
        }

        if (ch + 1 < NCH) { stsA((ch + 1) & 1); CPWAIT(0); }
        __syncthreads();
    }

    // ---- epilogues ----
    const int cc2 = cl * 2;
    float b0v[NT], b1v[NT];
#pragma unroll
    for (int nt = 0; nt < NT; nt++) {
        int n = nbase + wc * NWC + nt * 8 + cc2;
        b0v[nt] = bias[n];
        b1v[nt] = bias[n + 1];
    }

    if (PH) {
#pragma unroll
        for (int mt = 0; mt < 2; mt++)
#pragma unroll
            for (int rr = 0; rr < 2; rr++) {
                int row = m0 + wr * 32 + mt * 16 + r + rr * 8;
#pragma unroll
                for (int nt = 0; nt < NT; nt++) {
                    int n = nbase + wc * NWC + nt * 8 + cc2;
                    *(float2*)&outp[(size_t)row * 256 + n] = make_float2(
                        cf[mt][nt][rr * 2] + b0v[nt],
                        cf[mt][nt][rr * 2 + 1] + b1v[nt]);
                }
            }
        return;
    }

    if (mode == 2) {
        __half* tb = smh;   // [64][264]
#pragma unroll
        for (int mt = 0; mt < 2; mt++)
#pragma unroll
            for (int rr = 0; rr < 2; rr++) {
                int rowl = wr * 32 + mt * 16 + r + rr * 8;
#pragma unroll
                for (int nt = 0; nt < NT; nt++) {
                    int n = wc * NWC + nt * 8 + cc2;
                    *(unsigned*)&tb[rowl * 264 + n] = pkh(
                        cf[mt][nt][rr * 2 + 1] + b1v[nt],
                        cf[mt][nt][rr * 2] + b0v[nt]);
                }
            }
        __syncthreads();
        unsigned ur[32];
#pragma unroll
        for (int j = 0; j < 32; j++) {
            unsigned lo = __half_as_ushort(tb[(2 * j) * 264 + tid]);
            unsigned hi = __half_as_ushort(tb[(2 * j + 1) * 264 + tid]);
            ur[j] = lo | (hi << 16);
        }
        __half* dst = g_vthi + (size_t)tid * NK + m0;
#pragma unroll
        for (int j = 0; j < 8; j++) {
            uint4 v; v.x = ur[4 * j]; v.y = ur[4 * j + 1];
            v.z = ur[4 * j + 2]; v.w = ur[4 * j + 3];
            *(uint4*)(dst + 8 * j) = v;
        }
        return;
    }

    // modes 0 / 1: rope + fp16 store
    int nex = (mode == 1 && nex_ptr) ? *nex_ptr : 0;
    const int rope_limit = NK - nex;
    const int NN = (mode == 0) ? NQ : NK;
    __half* dsth = (mode == 0) ? g_qh : g_kh;

    float frv[NT];
#pragma unroll
    for (int nt = 0; nt < NT; nt++) {
        int p = ((wc * NWC + nt * 8 + cc2) & 63) >> 1;
        frv[nt] = ex2(-(float)(p & 15) * 1.6609640474f);
    }

#pragma unroll
    for (int mt = 0; mt < 2; mt++)
#pragma unroll
        for (int rr = 0; rr < 2; rr++) {
            int m = m0 + wr * 32 + mt * 16 + r + rr * 8;
            bool dorope = (mode == 0) || (m < rope_limit);
            int pos = (mode == 0) ? m : (m & (NQ - 1));
            float tx = (float)(pos & 63), ty = (float)(pos >> 6);
#pragma unroll
            for (int nt = 0; nt < NT; nt++) {
                float v0 = cf[mt][nt][rr * 2] + b0v[nt];
                float v1 = cf[mt][nt][rr * 2 + 1] + b1v[nt];
                int n = wc * NWC + nt * 8 + cc2;
                int d = n & 63, h = n >> 6;
                if (dorope) {
                    int p = d >> 1;
                    float t = (p < 16) ? tx : ty;
                    float sn, cs;
                    __sincosf(t * frv[nt], &sn, &cs);
                    float x0 = v0;
                    v0 = x0 * cs - v1 * sn;
                    v1 = v1 * cs + x0 * sn;
                }
                if (mode == 0) { v0 *= 0.125f; v1 *= 0.125f; }
                *(unsigned*)&dsth[((size_t)h * NN + m) * 64 + d] = pkh(v1, v0);
            }
        }
}

// ---------------- HMMA flash attention -------------------------------------
#define OKHI 0
#define OVHI 9216
#define BUFH 17920
#define SMEM_BYTES (2 * BUFH * 2)   // 71680

__device__ __forceinline__ void issue_tile(uint32_t sb, int buf, int kb,
    const __half* kh, const __half* vh, int tid)
{
    uint32_t base = sb + buf * (BUFH * 2);
#pragma unroll
    for (int i = 0; i < 4; i++) {
        int x = tid + i * 256;
        int krow = x >> 3, kch = x & 7;
        uint32_t kdst = base + (uint32_t)(krow * 72 + kch * 8) * 2;
        CP16(kdst + OKHI * 2, kh + (size_t)(kb + krow) * 64 + kch * 8);
        int vrow = x >> 4, vch = x & 15;
        uint32_t vdst = base + (uint32_t)(vrow * 136 + vch * 8) * 2;
        CP16(vdst + OVHI * 2, vh + (size_t)vrow * NK + kb + vch * 8);
    }
}

__global__ __launch_bounds__(256, 1) void attn_kernel()
{
    extern __shared__ char sm[];
    const uint32_t sb = smem_u32(sm);
    const int tid  = threadIdx.x;
    const int lane = tid & 31;
    const int w    = tid >> 5;
    const int qr   = w << 5;
    const int h    = blockIdx.y;
    const int z    = blockIdx.z;
    const int n0   = blockIdx.x << 8;

    const int a_row = (lane & 7) + ((lane >> 3) & 1) * 8;
    const int a_k   = (lane >> 4) * 8;
    const int b_row = lane & 7;
    const int b_k   = (lane >> 3) * 8;

    {
        const __half* qhp = g_qh + ((size_t)h * NQ + n0) * 64;
        for (int x = tid; x < 2048; x += 256) {
            int row = x >> 3, ch = x & 7;
            *(uint4*)(sm + (row * 72 + ch * 8) * 2) =
                *(const uint4*)(qhp + row * 64 + ch * 8);
        }
    }
    __syncthreads();

    uint32_t qf[2][4][4];
#pragma unroll
    for (int m = 0; m < 2; m++)
#pragma unroll
        for (int ks = 0; ks < 4; ks++)
            LDX4(qf[m][ks], sb + (uint32_t)((qr + m * 16 + a_row) * 72 + ks * 16 + a_k) * 2);
    __syncthreads();

    float of[2][8][4];
#pragma unroll
    for (int m = 0; m < 2; m++)
#pragma unroll
        for (int n = 0; n < 8; n++)
#pragma unroll
            for (int e = 0; e < 4; e++) of[m][n][e] = 0.f;
    float rs[2][2] = {{0.f, 0.f}, {0.f, 0.f}};

    const __half* kh = g_kh + ((size_t)h * NK + (size_t)z * KVLEN) * 64;
    const __half* vh = g_vthi + (size_t)h * 64 * NK + (size_t)z * KVLEN;

    issue_tile(sb, 0, 0, kh, vh, tid);
    CPCOMMIT();

    for (int kt = 0; kt < KVLEN / 128; kt++) {
        if (kt < KVLEN / 128 - 1) {
            issue_tile(sb, (kt + 1) & 1, (kt + 1) * 128, kh, vh, tid);
            CPCOMMIT();
            CPWAIT(1);
        } else {
            CPWAIT(0);
        }
        __syncthreads();

        const uint32_t base = sb + (uint32_t)(kt & 1) * (BUFH * 2);

#pragma unroll
        for (int hv = 0; hv < 2; hv++) {
            float sfs[2][2][2][4];
            uint32_t pf[2][4][4];

#pragma unroll
            for (int jp = 0; jp < 5; jp++) {
                if (jp < 4) {
                    float (*sc)[2][4] = sfs[jp & 1];
#pragma unroll
                    for (int m = 0; m < 2; m++)
#pragma unroll
                        for (int jj = 0; jj < 2; jj++)
#pragma unroll
                            for (int e = 0; e < 4; e++) sc[m][jj][e] = 0.f;

                    const int j0 = 2 * jp, j1 = 2 * jp + 1;
                    uint32_t bh0[8], bh1[8];
                    uint32_t ka0 = base + (uint32_t)((hv * 64 + j0 * 8 + b_row) * 72 + b_k) * 2;
                    uint32_t ka1 = base + (uint32_t)((hv * 64 + j1 * 8 + b_row) * 72 + b_k) * 2;
                    LDX4(bh0, ka0); LDX4(bh0 + 4, ka0 + 64);
                    LDX4(bh1, ka1); LDX4(bh1 + 4, ka1 + 64);
#pragma unroll
                    for (int ks = 0; ks < 4; ks++) {
                        MMAH(sc[0][0], qf[0][ks], bh0[2 * ks], bh0[2 * ks + 1]);
                        MMAH(sc[1][0], qf[1][ks], bh0[2 * ks], bh0[2 * ks + 1]);
                        MMAH(sc[0][1], qf[0][ks], bh1[2 * ks], bh1[2 * ks + 1]);
                        MMAH(sc[1][1], qf[1][ks], bh1[2 * ks], bh1[2 * ks + 1]);
                    }
                }
                if (jp > 0) {
                    float (*sp)[2][4] = sfs[(jp - 1) & 1];
                    const int kp = jp - 1;
#pragma unroll
                    for (int m = 0; m < 2; m++) {
                        float e00 = __expf(sp[m][0][0]);
                        float e01 = __expf(sp[m][0][1]);
                        float e02 = __expf(sp[m][0][2]);
                        float e03 = __expf(sp[m][0][3]);
                        float e10 = __expf(sp[m][1][0]);
                        float e11 = __expf(sp[m][1][1]);
                        float e12 = __expf(sp[m][1][2]);
                        float e13 = __expf(sp[m][1][3]);
                        rs[m][0] += e00 + e01 + e10 + e11;
                        rs[m][1] += e02 + e03 + e12 + e13;
                        pf[m][kp][0] = pkh(e01, e00);
                        pf[m][kp][1] = pkh(e03, e02);
                        pf[m][kp][2] = pkh(e11, e10);
                        pf[m][kp][3] = pkh(e13, e12);
                    }
                }
            }

#pragma unroll
            for (int np = 0; np < 4; np++) {
                const int d0 = 2 * np, d1 = 2 * np + 1;
                uint32_t vh0[8], vh1[8];
                uint32_t va0 = base + OVHI * 2 +
                               (uint32_t)((d0 * 8 + b_row) * 136 + hv * 64 + b_k) * 2;
                uint32_t va1 = base + OVHI * 2 +
                               (uint32_t)((d1 * 8 + b_row) * 136 + hv * 64 + b_k) * 2;
                LDX4(vh0, va0); LDX4(vh0 + 4, va0 + 64);
                LDX4(vh1, va1); LDX4(vh1 + 4, va1 + 64);
#pragma unroll
                for (int kp = 0; kp < 4; kp++) {
                    MMAH(of[0][d0], pf[0][kp], vh0[2 * kp], vh0[2 * kp + 1]);
                    MMAH(of[1][d0], pf[1][kp], vh0[2 * kp], vh0[2 * kp + 1]);
                    MMAH(of[0][d1], pf[0][kp], vh1[2 * kp], vh1[2 * kp + 1]);
                    MMAH(of[1][d1], pf[1][kp], vh1[2 * kp], vh1[2 * kp + 1]);
                }
            }
        }
        __syncthreads();
    }

#pragma unroll
    for (int m = 0; m < 2; m++)
#pragma unroll
        for (int rdx = 0; rdx < 2; rdx++) {
            rs[m][rdx] += __shfl_xor_sync(0xffffffffu, rs[m][rdx], 1);
            rs[m][rdx] += __shfl_xor_sync(0xffffffffu, rs[m][rdx], 2);
        }

    const int g = lane >> 2, tq = lane & 3;
    __half* po = g_poh + ((size_t)(z * HQ + h) * NQ + n0 + qr) * 64;
#pragma unroll
    for (int m = 0; m < 2; m++)
#pragma unroll
        for (int n = 0; n < 8; n++) {
            *(unsigned*)&po[(size_t)(m * 16 + g) * 64 + n * 8 + tq * 2] =
                pkh(of[m][n][1], of[m][n][0]);
            *(unsigned*)&po[(size_t)(m * 16 + g + 8) * 64 + n * 8 + tq * 2] =
                pkh(of[m][n][3], of[m][n][2]);
        }
    if (tq == 0) {
        float* pl = g_pl + (size_t)(z * HQ + h) * NQ + n0 + qr;
#pragma unroll
        for (int m = 0; m < 2; m++) {
            pl[m * 16 + g]     = rs[m][0];
            pl[m * 16 + g + 8] = rs[m][1];
        }
    }
}

// ---------------------------------------------------------------------------
extern "C" void kernel_launch(void* const* d_in, const int* in_sizes, int n_in,
                              void* d_out, int out_size)
{
    const float* query = (const float*)d_in[0];
    const float* key_  = (const float*)d_in[1];
    const float* value = (const float*)d_in[2];
    const float* Wq = (const float*)d_in[3];
    const float* bq = (const float*)d_in[4];
    const float* Wk = (const float*)d_in[5];
    const float* bk = (const float*)d_in[6];
    const float* Wv = (const float*)d_in[7];
    const float* bv = (const float*)d_in[8];
    const float* Wo = (const float*)d_in[9];
    const float* bo = (const float*)d_in[10];
    const int* nex = (n_in > 11) ? (const int*)d_in[11] : nullptr;
    float* out = (float*)d_out;

    cudaFuncSetAttribute(attn_kernel, cudaFuncAttributeMaxDynamicSharedMemorySize, SMEM_BYTES);
    cudaFuncSetAttribute(mm_kernel<0>, cudaFuncAttributeMaxDynamicSharedMemorySize, MM_SMEM);
    cudaFuncSetAttribute(mm_kernel<1>, cudaFuncAttributeMaxDynamicSharedMemorySize, MM_SMEM);

    wprep_kernel<<<160, 256>>>(Wq, Wk, Wv, Wo);
    mm_kernel<0><<<320, 256, MM_SMEM>>>(query, key_, value, bq, bk, bv, bo,
                                        nullptr, nex);
    attn_kernel<<<dim3(NQ / 256, HQ, KVS), 256, SMEM_BYTES>>>();
    mm_kernel<1><<<dim3(64, 2), 256, MM_SMEM>>>(query, key_, value, bq, bk, bv, bo,
                                                out, nullptr);
}

// round 14
// speedup vs baseline: 1.2166x; 1.0016x over previous
#include <cuda_runtime.h>
#include <cuda_fp16.h>
#include <cstdint>

#define HQ 4
#define NQ 4096
#define NK 8192
#define KVS 4           // kv splits
#define KVLEN (NK / KVS)

// ---------------- scratch (allocation-free __device__ globals) -------------
__device__ __align__(16) __half g_qh [HQ * NQ * 64];    // q fp16 (rope'd, /8)
__device__ __align__(16) __half g_kh [HQ * NK * 64];    // k fp16 (rope'd)
__device__ __align__(16) __half g_vthi[HQ * 64 * NK];   // [h][d][n]
__device__ __align__(16) __half g_poh[KVS * HQ * NQ * 64]; // partial O (fp16)
__device__ __align__(16) float g_pl[KVS * HQ * NQ];      // partial row sums
// pre-transposed + fp16-split weights: W^T [n=256][K]
__device__ __align__(16) __half g_wqh[256 * 256], g_wql[256 * 256];
__device__ __align__(16) __half g_wkh[256 * 64],  g_wkl[256 * 64];
__device__ __align__(16) __half g_wvh[256 * 64],  g_wvl[256 * 64];
__device__ __align__(16) __half g_woh[256 * 256], g_wol[256 * 256];

// ---------------- helpers ---------------------------------------------------
__device__ __forceinline__ uint32_t smem_u32(const void* p) {
    uint32_t a;
    asm("{ .reg .u64 t; cvta.to.shared.u64 t, %1; cvt.u32.u64 %0, t; }" : "=r"(a) : "l"(p));
    return a;
}
__device__ __forceinline__ unsigned pkh(float hi, float lo) {
    unsigned r;
    asm("cvt.rn.f16x2.f32 %0, %1, %2;" : "=r"(r) : "f"(hi), "f"(lo));
    return r;
}
__device__ __forceinline__ float h_lo(unsigned p) {
    return __half2float(__ushort_as_half((unsigned short)(p & 0xffff)));
}
__device__ __forceinline__ float h_hi(unsigned p) {
    return __half2float(__ushort_as_half((unsigned short)(p >> 16)));
}
__device__ __forceinline__ float ex2(float x) {
    float r;
    asm("ex2.approx.f32 %0, %1;" : "=f"(r) : "f"(x));
    return r;
}

#define LDX4(r, a) asm volatile( \
    "ldmatrix.sync.aligned.m8n8.x4.shared.b16 {%0,%1,%2,%3}, [%4];" \
    : "=r"((r)[0]), "=r"((r)[1]), "=r"((r)[2]), "=r"((r)[3]) : "r"(a))

#define MMAH(c, a, b0, b1) asm volatile( \
    "mma.sync.aligned.m16n8k16.row.col.f32.f16.f16.f32 " \
    "{%0,%1,%2,%3},{%4,%5,%6,%7},{%8,%9},{%0,%1,%2,%3};" \
    : "+f"((c)[0]), "+f"((c)[1]), "+f"((c)[2]), "+f"((c)[3]) \
    : "r"((a)[0]), "r"((a)[1]), "r"((a)[2]), "r"((a)[3]), "r"(b0), "r"(b1))

#define CP16(dst, src) asm volatile( \
    "cp.async.cg.shared.global [%0], [%1], 16;" :: "r"(dst), "l"(src))
#define CPCOMMIT() asm volatile("cp.async.commit_group;" ::: "memory")
#define CPWAIT(n)  asm volatile("cp.async.wait_group %0;" :: "n"(n) : "memory")

// ---------------- weight prep: transpose + fp16 hi/lo split ----------------
__global__ void wprep_kernel(const float* __restrict__ Wq,
                             const float* __restrict__ Wk,
                             const float* __restrict__ Wv,
                             const float* __restrict__ Wo)
{
    __shared__ float t[32][33];
    int bx = blockIdx.x;
    const float* W; __half *dh, *dl; int Kw;
    if (bx < 64)      { W = Wq; dh = g_wqh; dl = g_wql; Kw = 256; }
    else if (bx < 80) { W = Wk; dh = g_wkh; dl = g_wkl; Kw = 64;  bx -= 64; }
    else if (bx < 96) { W = Wv; dh = g_wvh; dl = g_wvl; Kw = 64;  bx -= 80; }
    else              { W = Wo; dh = g_woh; dl = g_wol; Kw = 256; bx -= 96; }
    const int ntk = Kw >> 5;
    const int tk = (bx % ntk) << 5, tn = (bx / ntk) << 5;
    const int tid = threadIdx.x;
    {
        int kl = tid >> 3, nl4 = (tid & 7) * 4;
        float4 v = *(const float4*)&W[(size_t)(tk + kl) * 256 + tn + nl4];
        t[kl][nl4] = v.x; t[kl][nl4 + 1] = v.y;
        t[kl][nl4 + 2] = v.z; t[kl][nl4 + 3] = v.w;
    }
    __syncthreads();
    int nl = tid >> 3, kq = (tid & 7) * 4;
    unsigned short hv[4], lv[4];
#pragma unroll
    for (int i = 0; i < 4; i++) {
        float x = t[kq + i][nl];
        __half hb = __float2half_rn(x);
        hv[i] = __half_as_ushort(hb);
        lv[i] = __half_as_ushort(__float2half_rn(x - __half2float(hb)));
    }
    size_t o = (size_t)(tn + nl) * Kw + tk + kq;
    *(uint2*)&dh[o] = make_uint2(hv[0] | (hv[1] << 16), hv[2] | (hv[3] << 16));
    *(uint2*)&dl[o] = make_uint2(lv[0] | (lv[1] << 16), lv[2] | (lv[3] << 16));
}

// ---------------- fp16-split tensor-core projection GEMM -------------------
#define SA 40
#define SW 40
#define AOFF(buf, pl) ((buf) * 5120 + (pl) * 2560)
#define WOFF(buf, pl) (10240 + (buf) * 20480 + (pl) * 10240)
#define MM_SMEM (51200 * 2)

template <int PH>
__global__ __launch_bounds__(256, 1) void mm_kernel(
    const float* __restrict__ Aq, const float* __restrict__ Ak,
    const float* __restrict__ Av,
    const float* __restrict__ bq, const float* __restrict__ bk,
    const float* __restrict__ bv, const float* __restrict__ bo,
    float* __restrict__ outp, const int* __restrict__ nex_ptr)
{
    extern __shared__ __half smh[];
    __shared__ float linv[256];
    const uint32_t sb = smem_u32(smh);

    constexpr int NT = PH ? 4 : 8;
    constexpr int NWC = PH ? 32 : 64;

    const int tid  = threadIdx.x;
    const int lane = tid & 31, w = tid >> 5;
    const int wr = w >> 2, wc = w & 3;
    const int r = lane >> 2, cl = lane & 3;
    const int a_row = (lane & 7) + ((lane >> 3) & 1) * 8;
    const int a_k   = (lane >> 4) * 8;
    const int b_row = lane & 7;
    const int b_k   = (lane >> 3) * 8;
    const int nbase = PH ? (blockIdx.y << 7) : 0;

    int mode, m0, Kd;
    const float *A = Aq, *bias;
    const __half *whi, *wlo;
    if (PH) {
        mode = 3; m0 = blockIdx.x << 6; Kd = 256;
        whi = g_woh; wlo = g_wol; bias = bo;
    } else {
        int bx = blockIdx.x;
        if (bx < 64)       { mode = 0; m0 = bx << 6;         Kd = 256; A = Aq; whi = g_wqh; wlo = g_wql; bias = bq; }
        else if (bx < 192) { mode = 1; m0 = (bx - 64) << 6;  Kd = 64;  A = Ak; whi = g_wkh; wlo = g_wkl; bias = bk; }
        else               { mode = 2; m0 = (bx - 192) << 6; Kd = 64;  A = Av; whi = g_wvh; wlo = g_wvl; bias = bv; }
    }

    if (PH) {
        int hh = tid >> 6, rl = tid & 63;
        float l = 0.f;
#pragma unroll
        for (int z = 0; z < KVS; z++)
            l += g_pl[(size_t)(z * HQ + hh) * NQ + m0 + rl];
        linv[tid] = 1.0f / l;
        __syncthreads();
    }

    const int NCH = Kd >> 5;
    const int arow = tid >> 2, acq = tid & 3;
    float4 ra0, ra1;

    auto ldgA = [&](int kc) {
        int k0 = kc + acq * 8;
        if (!PH) {
            ra0 = *(const float4*)&A[(size_t)(m0 + arow) * Kd + k0];
            ra1 = *(const float4*)&A[(size_t)(m0 + arow) * Kd + k0 + 4];
        } else {
            int hh = k0 >> 6, d = k0 & 63;
            size_t base = ((size_t)hh * NQ + m0 + arow) * 64 + d;
            uint4 v = *(const uint4*)&g_poh[base];
            __half2 s0 = *(__half2*)&v.x, s1 = *(__half2*)&v.y;
            __half2 s2 = *(__half2*)&v.z, s3 = *(__half2*)&v.w;
#pragma unroll
            for (int z = 1; z < KVS; z++) {
                uint4 p = *(const uint4*)&g_poh[(size_t)z * (HQ * NQ * 64) + base];
                s0 = __hadd2(s0, *(__half2*)&p.x);
                s1 = __hadd2(s1, *(__half2*)&p.y);
                s2 = __hadd2(s2, *(__half2*)&p.z);
                s3 = __hadd2(s3, *(__half2*)&p.w);
            }
            float iv = linv[hh * 64 + arow];
            ra0 = make_float4(__low2float(s0) * iv, __high2float(s0) * iv,
                              __low2float(s1) * iv, __high2float(s1) * iv);
            ra1 = make_float4(__low2float(s2) * iv, __high2float(s2) * iv,
                              __low2float(s3) * iv, __high2float(s3) * iv);
        }
    };

    auto stsA = [&](int buf) {
        unsigned h01 = pkh(ra0.y, ra0.x), h23 = pkh(ra0.w, ra0.z);
        unsigned h45 = pkh(ra1.y, ra1.x), h67 = pkh(ra1.w, ra1.z);
        unsigned l01 = pkh(ra0.y - h_hi(h01), ra0.x - h_lo(h01));
        unsigned l23 = pkh(ra0.w - h_hi(h23), ra0.z - h_lo(h23));
        unsigned l45 = pkh(ra1.y - h_hi(h45), ra1.x - h_lo(h45));
        unsigned l67 = pkh(ra1.w - h_hi(h67), ra1.z - h_lo(h67));
        int off = arow * SA + acq * 8;
        unsigned* ph = (unsigned*)&smh[AOFF(buf, 0) + off];
        ph[0] = h01; ph[1] = h23; ph[2] = h45; ph[3] = h67;
        unsigned* pl = (unsigned*)&smh[AOFF(buf, 1) + off];
        pl[0] = l01; pl[1] = l23; pl[2] = l45; pl[3] = l67;
    };

    auto cpW = [&](int kc, int buf) {
        const int NIT = PH ? 2 : 4;
#pragma unroll
        for (int i = 0; i < NIT; i++) {
            int idx = i * 256 + tid;
            int row = idx >> 2, seg = idx & 3;
            uint32_t d0 = sb + (uint32_t)(WOFF(buf, 0) + row * SW + seg * 8) * 2;
            uint32_t d1 = sb + (uint32_t)(WOFF(buf, 1) + row * SW + seg * 8) * 2;
            size_t so = (size_t)(nbase + row) * Kd + kc + seg * 8;
            CP16(d0, whi + so);
            CP16(d1, wlo + so);
        }
    };

    float cf[2][NT][4];
#pragma unroll
    for (int mt = 0; mt < 2; mt++)
#pragma unroll
        for (int nt = 0; nt < NT; nt++)
#pragma unroll
            for (int e = 0; e < 4; e++) cf[mt][nt][e] = 0.f;

    ldgA(0); cpW(0, 0); CPCOMMIT();
    stsA(0);
    CPWAIT(0);
    __syncthreads();

    for (int ch = 0; ch < NCH; ch++) {
        if (ch + 1 < NCH) { ldgA((ch + 1) << 5); cpW((ch + 1) << 5, (ch + 1) & 1); CPCOMMIT(); }

        const int buf = ch & 1;
        uint32_t af[2][2][2][4];
#pragma unroll
        for (int mt = 0; mt < 2; mt++)
#pragma unroll
            for (int ks = 0; ks < 2; ks++) {
                uint32_t aa = sb + (uint32_t)((wr * 32 + mt * 16 + a_row) * SA + ks * 16 + a_k) * 2;
                LDX4(af[0][mt][ks], aa + AOFF(buf, 0) * 2);
                LDX4(af[1][mt][ks], aa + AOFF(buf, 1) * 2);
            }
#pragma unroll
        for (int nt = 0; nt < NT; nt++) {
            uint32_t bh[4], bl[4];
            uint32_t wa = sb + (uint32_t)(WOFF(buf, 0) + (wc * NWC + nt * 8 + b_row) * SW + b_k) * 2;
            LDX4(bh, wa);
            LDX4(bl, wa + 10240 * 2);
#pragma unroll
            for (int ks = 0; ks < 2; ks++) {
                MMAH(cf[0][nt], af[0][0][ks], bh[2 * ks], bh[2 * ks + 1]);
                MMAH(cf[1][nt], af[0][1][ks], bh[2 * ks], bh[2 * ks + 1]);
                MMAH(cf[0][nt], af[0][0][ks], bl[2 * ks], bl[2 * ks + 1]);
                MMAH(cf[1][nt], af[0][1][ks], bl[2 * ks], bl[2 * ks + 1]);
                MMAH(cf[0][nt], af[1][0][ks], bh[2 * ks], bh[2 * ks + 1]);
                MMAH(cf[1][nt], af[1][1][ks], bh[2 * ks], bh[2 * ks + 1]);
            }
        }

        if (ch + 1 < NCH) { stsA((ch + 1) & 1); CPWAIT(0); }
        __syncthreads();
    }

    // ---- epilogues ----
    const int cc2 = cl * 2;
    float b0v[NT], b1v[NT];
#pragma unroll
    for (int nt = 0; nt < NT; nt++) {
        int n = nbase + wc * NWC + nt * 8 + cc2;
        b0v[nt] = bias[n];
        b1v[nt] = bias[n + 1];
    }

    if (PH) {
#pragma unroll
        for (int mt = 0; mt < 2; mt++)
#pragma unroll
            for (int rr = 0; rr < 2; rr++) {
                int row = m0 + wr * 32 + mt * 16 + r + rr * 8;
#pragma unroll
                for (int nt = 0; nt < NT; nt++) {
                    int n = nbase + wc * NWC + nt * 8 + cc2;
                    *(float2*)&outp[(size_t)row * 256 + n] = make_float2(
                        cf[mt][nt][rr * 2] + b0v[nt],
                        cf[mt][nt][rr * 2 + 1] + b1v[nt]);
                }
            }
        return;
    }

    if (mode == 2) {
        __half* tb = smh;   // [64][264]
#pragma unroll
        for (int mt = 0; mt < 2; mt++)
#pragma unroll
            for (int rr = 0; rr < 2; rr++) {
                int rowl = wr * 32 + mt * 16 + r + rr * 8;
#pragma unroll
                for (int nt = 0; nt < NT; nt++) {
                    int n = wc * NWC + nt * 8 + cc2;
                    *(unsigned*)&tb[rowl * 264 + n] = pkh(
                        cf[mt][nt][rr * 2 + 1] + b1v[nt],
                        cf[mt][nt][rr * 2] + b0v[nt]);
                }
            }
        __syncthreads();
        unsigned ur[32];
#pragma unroll
        for (int j = 0; j < 32; j++) {
            unsigned lo = __half_as_ushort(tb[(2 * j) * 264 + tid]);
            unsigned hi = __half_as_ushort(tb[(2 * j + 1) * 264 + tid]);
            ur[j] = lo | (hi << 16);
        }
        __half* dst = g_vthi + (size_t)tid * NK + m0;
#pragma unroll
        for (int j = 0; j < 8; j++) {
            uint4 v; v.x = ur[4 * j]; v.y = ur[4 * j + 1];
            v.z = ur[4 * j + 2]; v.w = ur[4 * j + 3];
            *(uint4*)(dst + 8 * j) = v;
        }
        return;
    }

    // modes 0 / 1: rope + fp16 store
    int nex = (mode == 1 && nex_ptr) ? *nex_ptr : 0;
    const int rope_limit = NK - nex;
    const int NN = (mode == 0) ? NQ : NK;
    __half* dsth = (mode == 0) ? g_qh : g_kh;

    float frv[NT];
#pragma unroll
    for (int nt = 0; nt < NT; nt++) {
        int p = ((wc * NWC + nt * 8 + cc2) & 63) >> 1;
        frv[nt] = ex2(-(float)(p & 15) * 1.6609640474f);
    }

#pragma unroll
    for (int mt = 0; mt < 2; mt++)
#pragma unroll
        for (int rr = 0; rr < 2; rr++) {
            int m = m0 + wr * 32 + mt * 16 + r + rr * 8;
            bool dorope = (mode == 0) || (m < rope_limit);
            int pos = (mode == 0) ? m : (m & (NQ - 1));
            float tx = (float)(pos & 63), ty = (float)(pos >> 6);
#pragma unroll
            for (int nt = 0; nt < NT; nt++) {
                float v0 = cf[mt][nt][rr * 2] + b0v[nt];
                float v1 = cf[mt][nt][rr * 2 + 1] + b1v[nt];
                int n = wc * NWC + nt * 8 + cc2;
                int d = n & 63, h = n >> 6;
                if (dorope) {
                    int p = d >> 1;
                    float t = (p < 16) ? tx : ty;
                    float sn, cs;
                    __sincosf(t * frv[nt], &sn, &cs);
                    float x0 = v0;
                    v0 = x0 * cs - v1 * sn;
                    v1 = v1 * cs + x0 * sn;
                }
                if (mode == 0) { v0 *= 0.125f; v1 *= 0.125f; }
                *(unsigned*)&dsth[((size_t)h * NN + m) * 64 + d] = pkh(v1, v0);
            }
        }
}

// ---------------- HMMA flash attention: 128 threads, 2 CTAs/SM -------------
// Grid (32, HQ, KVS): CTA = 128 q rows x head x kv-slice. 4 warps, warp owns
// 32 q rows. Two independent CTAs co-resident per SM dephase MUFU/tensor.
#define OKHI 0
#define OVHI 9216
#define BUFH 17920
#define SMEM_BYTES (2 * BUFH * 2)   // 71680

__device__ __forceinline__ void issue_tile(uint32_t sb, int buf, int kb,
    const __half* kh, const __half* vh, int tid)
{
    uint32_t base = sb + buf * (BUFH * 2);
#pragma unroll
    for (int i = 0; i < 8; i++) {
        int x = tid + i * 128;
        int krow = x >> 3, kch = x & 7;
        uint32_t kdst = base + (uint32_t)(krow * 72 + kch * 8) * 2;
        CP16(kdst + OKHI * 2, kh + (size_t)(kb + krow) * 64 + kch * 8);
        int vrow = x >> 4, vch = x & 15;
        uint32_t vdst = base + (uint32_t)(vrow * 136 + vch * 8) * 2;
        CP16(vdst + OVHI * 2, vh + (size_t)vrow * NK + kb + vch * 8);
    }
}

__global__ __launch_bounds__(128, 2) void attn_kernel()
{
    extern __shared__ char sm[];
    const uint32_t sb = smem_u32(sm);
    const int tid  = threadIdx.x;
    const int lane = tid & 31;
    const int w    = tid >> 5;          // 0..3
    const int qr   = w << 5;            // 32 q rows per warp
    const int h    = blockIdx.y;
    const int z    = blockIdx.z;
    const int n0   = blockIdx.x << 7;   // 128 q rows per CTA

    const int a_row = (lane & 7) + ((lane >> 3) & 1) * 8;
    const int a_k   = (lane >> 4) * 8;
    const int b_row = lane & 7;
    const int b_k   = (lane >> 3) * 8;

    // ---- stage Q (128 x 64 fp16) into smem, preload A-fragments ----
    {
        const __half* qhp = g_qh + ((size_t)h * NQ + n0) * 64;
        for (int x = tid; x < 1024; x += 128) {
            int row = x >> 3, ch = x & 7;
            *(uint4*)(sm + (row * 72 + ch * 8) * 2) =
                *(const uint4*)(qhp + row * 64 + ch * 8);
        }
    }
    __syncthreads();

    uint32_t qf[2][4][4];
#pragma unroll
    for (int m = 0; m < 2; m++)
#pragma unroll
        for (int ks = 0; ks < 4; ks++)
            LDX4(qf[m][ks], sb + (uint32_t)((qr + m * 16 + a_row) * 72 + ks * 16 + a_k) * 2);
    __syncthreads();

    float of[2][8][4];
#pragma unroll
    for (int m = 0; m < 2; m++)
#pragma unroll
        for (int n = 0; n < 8; n++)
#pragma unroll
            for (int e = 0; e < 4; e++) of[m][n][e] = 0.f;
    float rs[2][2] = {{0.f, 0.f}, {0.f, 0.f}};

    const __half* kh = g_kh + ((size_t)h * NK + (size_t)z * KVLEN) * 64;
    const __half* vh = g_vthi + (size_t)h * 64 * NK + (size_t)z * KVLEN;

    issue_tile(sb, 0, 0, kh, vh, tid);
    CPCOMMIT();

    for (int kt = 0; kt < KVLEN / 128; kt++) {
        if (kt < KVLEN / 128 - 1) {
            issue_tile(sb, (kt + 1) & 1, (kt + 1) * 128, kh, vh, tid);
            CPCOMMIT();
            CPWAIT(1);
        } else {
            CPWAIT(0);
        }
        __syncthreads();

        const uint32_t base = sb + (uint32_t)(kt & 1) * (BUFH * 2);

#pragma unroll
        for (int hv = 0; hv < 2; hv++) {
            // ---- S = Q K^T pipelined with exp/pack (2-stage, jp granular)
            float sfs[2][2][2][4];
            uint32_t pf[2][4][4];

#pragma unroll
            for (int jp = 0; jp < 5; jp++) {
                if (jp < 4) {
                    float (*sc)[2][4] = sfs[jp & 1];
#pragma unroll
                    for (int m = 0; m < 2; m++)
#pragma unroll
                        for (int jj = 0; jj < 2; jj++)
#pragma unroll
                            for (int e = 0; e < 4; e++) sc[m][jj][e] = 0.f;

                    const int j0 = 2 * jp, j1 = 2 * jp + 1;
                    uint32_t bh0[8], bh1[8];
                    uint32_t ka0 = base + (uint32_t)((hv * 64 + j0 * 8 + b_row) * 72 + b_k) * 2;
                    uint32_t ka1 = base + (uint32_t)((hv * 64 + j1 * 8 + b_row) * 72 + b_k) * 2;
                    LDX4(bh0, ka0); LDX4(bh0 + 4, ka0 + 64);
                    LDX4(bh1, ka1); LDX4(bh1 + 4, ka1 + 64);
#pragma unroll
                    for (int ks = 0; ks < 4; ks++) {
                        MMAH(sc[0][0], qf[0][ks], bh0[2 * ks], bh0[2 * ks + 1]);
                        MMAH(sc[1][0], qf[1][ks], bh0[2 * ks], bh0[2 * ks + 1]);
                        MMAH(sc[0][1], qf[0][ks], bh1[2 * ks], bh1[2 * ks + 1]);
                        MMAH(sc[1][1], qf[1][ks], bh1[2 * ks], bh1[2 * ks + 1]);
                    }
                }
                if (jp > 0) {
                    float (*sp)[2][4] = sfs[(jp - 1) & 1];
                    const int kp = jp - 1;
#pragma unroll
                    for (int m = 0; m < 2; m++) {
                        float e00 = __expf(sp[m][0][0]);
                        float e01 = __expf(sp[m][0][1]);
                        float e02 = __expf(sp[m][0][2]);
                        float e03 = __expf(sp[m][0][3]);
                        float e10 = __expf(sp[m][1][0]);
                        float e11 = __expf(sp[m][1][1]);
                        float e12 = __expf(sp[m][1][2]);
                        float e13 = __expf(sp[m][1][3]);
                        rs[m][0] += e00 + e01 + e10 + e11;
                        rs[m][1] += e02 + e03 + e12 + e13;
                        pf[m][kp][0] = pkh(e01, e00);
                        pf[m][kp][1] = pkh(e03, e02);
                        pf[m][kp][2] = pkh(e11, e10);
                        pf[m][kp][3] = pkh(e13, e12);
                    }
                }
            }

            // ---- O += P V ----
#pragma unroll
            for (int np = 0; np < 4; np++) {
                const int d0 = 2 * np, d1 = 2 * np + 1;
                uint32_t vh0[8], vh1[8];
                uint32_t va0 = base + OVHI * 2 +
                               (uint32_t)((d0 * 8 + b_row) * 136 + hv * 64 + b_k) * 2;
                uint32_t va1 = base + OVHI * 2 +
                               (uint32_t)((d1 * 8 + b_row) * 136 + hv * 64 + b_k) * 2;
                LDX4(vh0, va0); LDX4(vh0 + 4, va0 + 64);
                LDX4(vh1, va1); LDX4(vh1 + 4, va1 + 64);
#pragma unroll
                for (int kp = 0; kp < 4; kp++) {
                    MMAH(of[0][d0], pf[0][kp], vh0[2 * kp], vh0[2 * kp + 1]);
                    MMAH(of[1][d0], pf[1][kp], vh0[2 * kp], vh0[2 * kp + 1]);
                    MMAH(of[0][d1], pf[0][kp], vh1[2 * kp], vh1[2 * kp + 1]);
                    MMAH(of[1][d1], pf[1][kp], vh1[2 * kp], vh1[2 * kp + 1]);
                }
            }
        }
        __syncthreads();
    }

    // ---- epilogue: quad-reduce row sums, store fp16 partials ----
#pragma unroll
    for (int m = 0; m < 2; m++)
#pragma unroll
        for (int rdx = 0; rdx < 2; rdx++) {
            rs[m][rdx] += __shfl_xor_sync(0xffffffffu, rs[m][rdx], 1);
            rs[m][rdx] += __shfl_xor_sync(0xffffffffu, rs[m][rdx], 2);
        }

    const int g = lane >> 2, tq = lane & 3;
    __half* po = g_poh + ((size_t)(z * HQ + h) * NQ + n0 + qr) * 64;
#pragma unroll
    for (int m = 0; m < 2; m++)
#pragma unroll
        for (int n = 0; n < 8; n++) {
            *(unsigned*)&po[(size_t)(m * 16 + g) * 64 + n * 8 + tq * 2] =
                pkh(of[m][n][1], of[m][n][0]);
            *(unsigned*)&po[(size_t)(m * 16 + g + 8) * 64 + n * 8 + tq * 2] =
                pkh(of[m][n][3], of[m][n][2]);
        }
    if (tq == 0) {
        float* pl = g_pl + (size_t)(z * HQ + h) * NQ + n0 + qr;
#pragma unroll
        for (int m = 0; m < 2; m++) {
            pl[m * 16 + g]     = rs[m][0];
            pl[m * 16 + g + 8] = rs[m][1];
        }
    }
}

// ---------------------------------------------------------------------------
extern "C" void kernel_launch(void* const* d_in, const int* in_sizes, int n_in,
                              void* d_out, int out_size)
{
    const float* query = (const float*)d_in[0];
    const float* key_  = (const float*)d_in[1];
    const float* value = (const float*)d_in[2];
    const float* Wq = (const float*)d_in[3];
    const float* bq = (const float*)d_in[4];
    const float* Wk = (const float*)d_in[5];
    const float* bk = (const float*)d_in[6];
    const float* Wv = (const float*)d_in[7];
    const float* bv = (const float*)d_in[8];
    const float* Wo = (const float*)d_in[9];
    const float* bo = (const float*)d_in[10];
    const int* nex = (n_in > 11) ? (const int*)d_in[11] : nullptr;
    float* out = (float*)d_out;

    cudaFuncSetAttribute(attn_kernel, cudaFuncAttributeMaxDynamicSharedMemorySize, SMEM_BYTES);
    cudaFuncSetAttribute(mm_kernel<0>, cudaFuncAttributeMaxDynamicSharedMemorySize, MM_SMEM);
    cudaFuncSetAttribute(mm_kernel<1>, cudaFuncAttributeMaxDynamicSharedMemorySize, MM_SMEM);

    wprep_kernel<<<160, 256>>>(Wq, Wk, Wv, Wo);
    mm_kernel<0><<<320, 256, MM_SMEM>>>(query, key_, value, bq, bk, bv, bo,
                                        nullptr, nex);
    attn_kernel<<<dim3(NQ / 128, HQ, KVS), 128, SMEM_BYTES>>>();
    mm_kernel<1><<<dim3(64, 2), 256, MM_SMEM>>>(query, key_, value, bq, bk, bv, bo,
                                                out, nullptr);
}